// round 3
// baseline (speedup 1.0000x reference)
#include <cuda_runtime.h>
#include <math_constants.h>

#define S_LEN  2048
#define DIM    4096
#define KV_DIM 1024
#define NH     32
#define NKV    8
#define HD     128

// ---------------- scratch (module-load allocated; no runtime allocs) --------
__device__ __align__(16) float g_q[S_LEN * DIM];        // 32 MB
__device__ __align__(16) float g_k[S_LEN * KV_DIM];     //  8 MB
__device__ __align__(16) float g_v[S_LEN * KV_DIM];     //  8 MB
__device__ __align__(16) float g_attn[S_LEN * DIM];     // 32 MB
__device__ __align__(16) float g_s[134217728];          // 512 MB: [32][2048][2048]

// ---------------- f32x2 packed-FMA helpers (Blackwell FFMA2 path) -----------
typedef unsigned long long u64;
union F2U { u64 u; float2 f; };

__device__ __forceinline__ u64 pk2(float x, float y) {
    u64 r; asm("mov.b64 %0, {%1, %2};" : "=l"(r) : "f"(x), "f"(y)); return r;
}
__device__ __forceinline__ u64 ffma2(u64 a, u64 b, u64 c) {
    u64 d; asm("fma.rn.f32x2 %0, %1, %2, %3;" : "=l"(d) : "l"(a), "l"(b), "l"(c)); return d;
}

// ---------------- shared-tile MAC core: 128x128 C-tile, BK=16, 256 thr ------
// Each thread owns an 8x8 sub-tile, accumulated as 8x4 f32x2 pairs.
__device__ __forceinline__ void tile_mac(const float (&As)[16][128],
                                         const float (&Bs)[16][128],
                                         int tm, int tn, u64 (&acc)[8][4]) {
#pragma unroll
    for (int kk = 0; kk < 16; kk++) {
        float4 a0 = *(const float4*)&As[kk][tm];
        float4 a1 = *(const float4*)&As[kk][tm + 4];
        float a_[8] = {a0.x, a0.y, a0.z, a0.w, a1.x, a1.y, a1.z, a1.w};
        ulonglong2 p0 = *(const ulonglong2*)&Bs[kk][tn];
        ulonglong2 p1 = *(const ulonglong2*)&Bs[kk][tn + 4];
        u64 b_[4] = {p0.x, p0.y, p1.x, p1.y};
#pragma unroll
        for (int i = 0; i < 8; i++) {
            u64 ad = pk2(a_[i], a_[i]);
#pragma unroll
            for (int j = 0; j < 4; j++) acc[i][j] = ffma2(ad, b_[j], acc[i][j]);
        }
    }
}

// Load a [128 x 16] K-major panel and store transposed to Sm[k][m].
__device__ __forceinline__ void load_tile_kmajor(const float* __restrict__ P, int ldp,
                                                 int k0, float (&Sm)[16][128], int tid) {
#pragma unroll
    for (int l = 0; l < 2; l++) {
        int i = tid + l * 256;
        int m = i >> 2, kq = (i & 3) << 2;
        float4 v = *(const float4*)(P + (size_t)m * ldp + k0 + kq);
        Sm[kq + 0][m] = v.x; Sm[kq + 1][m] = v.y;
        Sm[kq + 2][m] = v.z; Sm[kq + 3][m] = v.w;
    }
}

__device__ __forceinline__ void store_plain(u64 (&acc)[8][4], float* Cb, int ldc) {
#pragma unroll
    for (int i = 0; i < 8; i++)
#pragma unroll
        for (int j = 0; j < 4; j++) {
            F2U t; t.u = acc[i][j];
            *(float2*)(Cb + (size_t)i * ldc + 2 * j) = t.f;
        }
}

// ---------------- generic C = A[M,K] * B[N,K]^T  (both K-major) -------------
__global__ __launch_bounds__(256) void gemm_nt(const float* __restrict__ A, int lda,
                                               const float* __restrict__ B, int ldb,
                                               float* __restrict__ C, int ldc, int K) {
    __shared__ __align__(16) float As[16][128];
    __shared__ __align__(16) float Bs[16][128];
    int tid = threadIdx.x;
    int tm = (tid >> 4) << 3, tn = (tid & 15) << 3;
    const float* Ab = A + (size_t)blockIdx.x * 128 * lda;
    const float* Bb = B + (size_t)blockIdx.y * 128 * ldb;
    u64 acc[8][4] = {};
    for (int k0 = 0; k0 < K; k0 += 16) {
        load_tile_kmajor(Ab, lda, k0, As, tid);
        load_tile_kmajor(Bb, ldb, k0, Bs, tid);
        __syncthreads();
        tile_mac(As, Bs, tm, tn, acc);
        __syncthreads();
    }
    float* Cb = C + ((size_t)blockIdx.x * 128 + tm) * ldc + blockIdx.y * 128 + tn;
    store_plain(acc, Cb, ldc);
}

// ---------------- RoPE (in place), interleaved pairs ------------------------
__global__ void rope_kernel(float* __restrict__ buf, const float* __restrict__ fc,
                            const float* __restrict__ fs, int n_heads, int rstride,
                            int total) {
    int idx = blockIdx.x * blockDim.x + threadIdx.x;
    if (idx >= total) return;
    int i = idx & 63;
    int h = (idx >> 6) & (n_heads - 1);
    int s = idx / (n_heads << 6);
    float c  = fc[(s << 6) + i];
    float sn = fs[(s << 6) + i];
    size_t base = (size_t)s * rstride + (h << 7) + (i << 1);
    float2 v = *(float2*)(buf + base);
    float2 o;
    o.x = v.x * c - v.y * sn;
    o.y = v.x * sn + v.y * c;
    *(float2*)(buf + base) = o;
}

// ---------------- scores = scale * Qh Kh^T, causal-skipped ------------------
__global__ __launch_bounds__(256) void score_kernel(const float* __restrict__ Qb,
                                                    const float* __restrict__ Kb,
                                                    float* __restrict__ Sb) {
    int bx = blockIdx.x, by = blockIdx.y;
    if (by > bx) return;            // strictly-upper causal blocks never touched
    int h = blockIdx.z;
    __shared__ __align__(16) float As[16][128];
    __shared__ __align__(16) float Bs[16][128];
    int tid = threadIdx.x;
    int tm = (tid >> 4) << 3, tn = (tid & 15) << 3;
    const float* Ab = Qb + (size_t)bx * 128 * DIM + h * HD;
    const float* Bb = Kb + (size_t)by * 128 * KV_DIM + (h >> 2) * HD;
    u64 acc[8][4] = {};
#pragma unroll
    for (int k0 = 0; k0 < HD; k0 += 16) {
        load_tile_kmajor(Ab, DIM, k0, As, tid);
        load_tile_kmajor(Bb, KV_DIM, k0, Bs, tid);
        __syncthreads();
        tile_mac(As, Bs, tm, tn, acc);
        __syncthreads();
    }
    const float scale = 0.088388347648318447f;   // 1/sqrt(128)
    float* Cb = Sb + ((size_t)h * S_LEN + (size_t)bx * 128 + tm) * S_LEN + by * 128 + tn;
    bool diag = (bx == by);
    int qrow = bx * 128 + tm, kcol = by * 128 + tn;
#pragma unroll
    for (int i = 0; i < 8; i++)
#pragma unroll
        for (int j = 0; j < 4; j++) {
            F2U t; t.u = acc[i][j];
            float v0 = t.f.x * scale, v1 = t.f.y * scale;
            if (diag) {
                if (kcol + 2 * j     > qrow + i) v0 = -CUDART_INF_F;
                if (kcol + 2 * j + 1 > qrow + i) v1 = -CUDART_INF_F;
            }
            t.f.x = v0; t.f.y = v1;
            *(float2*)(Cb + (size_t)i * S_LEN + 2 * j) = t.f;
        }
}

// ---------------- FFMA-only exp (avoids 1ms of MUFU.EX2) --------------------
__device__ __forceinline__ float fexp(float x) {
    float y = fmaxf(x * 1.4426950408889634f, -126.0f);
    float fl = floorf(y);
    float f = y - fl;
    float p = 1.5403530e-4f;
    p = fmaf(p, f, 1.3333558e-3f);
    p = fmaf(p, f, 9.6181291e-3f);
    p = fmaf(p, f, 5.5504109e-2f);
    p = fmaf(p, f, 2.4022651e-1f);
    p = fmaf(p, f, 6.9314718e-1f);
    p = fmaf(p, f, 1.0f);
    int e = (int)fl;
    return __int_as_float((e + 127) << 23) * p;
}

// ---------------- in-place causal softmax, one 128-thr block per row --------
__global__ __launch_bounds__(128) void softmax_kernel(float* __restrict__ Sb) {
    int q = blockIdx.x, h = blockIdx.y;
    int n = (q >> 7) + 1;                        // row processed up to tile edge
    float* row = Sb + ((size_t)h * S_LEN + q) * S_LEN;
    int tid = threadIdx.x;
    float v[16];
    float m = -CUDART_INF_F;
    for (int c = 0; c < n; c++) { v[c] = row[(c << 7) + tid]; m = fmaxf(m, v[c]); }
#pragma unroll
    for (int o = 16; o; o >>= 1) m = fmaxf(m, __shfl_xor_sync(~0u, m, o));
    __shared__ float red[4];
    if ((tid & 31) == 0) red[tid >> 5] = m;
    __syncthreads();
    m = fmaxf(fmaxf(red[0], red[1]), fmaxf(red[2], red[3]));
    __syncthreads();
    float s = 0.f;
    for (int c = 0; c < n; c++) { v[c] = fexp(v[c] - m); s += v[c]; }
#pragma unroll
    for (int o = 16; o; o >>= 1) s += __shfl_xor_sync(~0u, s, o);
    if ((tid & 31) == 0) red[tid >> 5] = s;
    __syncthreads();
    s = red[0] + red[1] + red[2] + red[3];
    float inv = __fdividef(1.0f, s);
    for (int c = 0; c < n; c++) row[(c << 7) + tid] = v[c] * inv;
}

// ---------------- out_h = P[q, 0..L) @ Vh[0..L, 128]  (NN, K-limited) -------
__global__ __launch_bounds__(256) void pv_kernel(const float* __restrict__ Pb,
                                                 const float* __restrict__ Vb,
                                                 float* __restrict__ Ob) {
    int t = blockIdx.x, h = blockIdx.y;
    __shared__ __align__(16) float As[16][128];
    __shared__ __align__(16) float Bs[16][128];
    int tid = threadIdx.x;
    int tm = (tid >> 4) << 3, tn = (tid & 15) << 3;
    const float* Ab = Pb + ((size_t)h * S_LEN + (size_t)t * 128) * S_LEN;
    const float* Bb = Vb + (h >> 2) * HD;
    int L = (t + 1) * 128;                       // causal K-limit for this q-tile
    u64 acc[8][4] = {};
    for (int k0 = 0; k0 < L; k0 += 16) {
        load_tile_kmajor(Ab, S_LEN, k0, As, tid);
#pragma unroll
        for (int l = 0; l < 2; l++) {
            int i4 = tid + l * 256;
            int r = i4 >> 5, c4 = (i4 & 31) << 2;
            *(float4*)&Bs[r][c4] = *(const float4*)(Bb + (size_t)(k0 + r) * KV_DIM + c4);
        }
        __syncthreads();
        tile_mac(As, Bs, tm, tn, acc);
        __syncthreads();
    }
    float* Cb = Ob + ((size_t)t * 128 + tm) * DIM + h * HD + tn;
    store_plain(acc, Cb, DIM);
}

// ---------------- launch ----------------------------------------------------
extern "C" void kernel_launch(void* const* d_in, const int* in_sizes, int n_in,
                              void* d_out, int out_size) {
    const float* x  = (const float*)d_in[0];
    const float* wq = (const float*)d_in[1];
    const float* wk = (const float*)d_in[2];
    const float* wv = (const float*)d_in[3];
    const float* wo = (const float*)d_in[4];
    const float* fc = (const float*)d_in[5];
    const float* fs = (const float*)d_in[6];
    float* out = (float*)d_out;

    float *Q, *K, *V, *AT, *S;
    cudaGetSymbolAddress((void**)&Q,  g_q);
    cudaGetSymbolAddress((void**)&K,  g_k);
    cudaGetSymbolAddress((void**)&V,  g_v);
    cudaGetSymbolAddress((void**)&AT, g_attn);
    cudaGetSymbolAddress((void**)&S,  g_s);

    // QKV projections:  C[M,N] = A[M,K] * B[N,K]^T
    gemm_nt<<<dim3(S_LEN / 128, DIM / 128),    256>>>(x, DIM, wq, DIM, Q, DIM,    DIM);
    gemm_nt<<<dim3(S_LEN / 128, KV_DIM / 128), 256>>>(x, DIM, wk, DIM, K, KV_DIM, DIM);
    gemm_nt<<<dim3(S_LEN / 128, KV_DIM / 128), 256>>>(x, DIM, wv, DIM, V, KV_DIM, DIM);

    // RoPE on Q and K (in place)
    rope_kernel<<<(S_LEN * NH  * 64 + 255) / 256, 256>>>(Q, fc, fs, NH,  DIM,    S_LEN * NH  * 64);
    rope_kernel<<<(S_LEN * NKV * 64 + 255) / 256, 256>>>(K, fc, fs, NKV, KV_DIM, S_LEN * NKV * 64);

    // scores (causal-skipped) -> softmax (in place) -> P@V
    score_kernel<<<dim3(16, 16, NH), 256>>>(Q, K, S);
    softmax_kernel<<<dim3(S_LEN, NH), 128>>>(S);
    pv_kernel<<<dim3(16, NH), 256>>>(S, V, AT);

    // output projection
    gemm_nt<<<dim3(S_LEN / 128, DIM / 128), 256>>>(AT, DIM, wo, DIM, out, DIM, DIM);
}

// round 9
// speedup vs baseline: 1.8902x; 1.8902x over previous
#include <cuda_runtime.h>
#include <cuda_bf16.h>
#include <math_constants.h>
#include <cstdint>

#define S_LEN  2048
#define DIM    4096
#define KV_DIM 1024
#define NH     32
#define NKV    8
#define HD     128
#define K3DIM  12288      // 3*4096 (tripled K for projections)
#define K3HD   384        // 3*128  (tripled K for scores)
#define K3S    6144       // 3*2048 (tripled K for PV)
#define BK     32
#define SMS    40         // smem row stride in bf16 (32 + 8 pad; 80B, 16B-aligned)

// ---------------- scratch (module-load allocated) ---------------------------
__device__ __align__(16) float g_q[S_LEN * DIM];
__device__ __align__(16) float g_k[S_LEN * KV_DIM];
__device__ __align__(16) float g_v[S_LEN * KV_DIM];
__device__ __align__(16) float g_s[(size_t)NH * S_LEN * S_LEN];          // fp32 scores
__device__ __align__(16) __nv_bfloat16 g_x3 [S_LEN * K3DIM];
__device__ __align__(16) __nv_bfloat16 g_wq3[DIM * K3DIM];
__device__ __align__(16) __nv_bfloat16 g_wk3[KV_DIM * K3DIM];
__device__ __align__(16) __nv_bfloat16 g_wv3[KV_DIM * K3DIM];
__device__ __align__(16) __nv_bfloat16 g_wo3[DIM * K3DIM];
__device__ __align__(16) __nv_bfloat16 g_q3 [S_LEN * K3DIM];             // roped, A-pat
__device__ __align__(16) __nv_bfloat16 g_k3 [S_LEN * (NKV * K3HD)];      // roped, B-pat
__device__ __align__(16) __nv_bfloat16 g_vt3[KV_DIM * K3S];              // V^T, B-pat
__device__ __align__(16) __nv_bfloat16 g_p3 [(size_t)NH * S_LEN * K3S];  // probs, A-pat
__device__ __align__(16) __nv_bfloat16 g_at3[S_LEN * K3DIM];             // attn out, A-pat

// ---------------- helpers ----------------------------------------------------
__device__ __forceinline__ void split2(float a, __nv_bfloat16& hi, __nv_bfloat16& lo) {
    hi = __float2bfloat16(a);
    lo = __float2bfloat16(a - __bfloat162float(hi));
}
__device__ __forceinline__ uint32_t s2u(const void* p) {
    uint32_t a;
    asm("{ .reg .u64 t; cvta.to.shared.u64 t, %1; cvt.u32.u64 %0, t; }" : "=r"(a) : "l"(p));
    return a;
}
__device__ __forceinline__ void cpa16(uint32_t s, const void* g) {
    asm volatile("cp.async.cg.shared.global [%0], [%1], 16;" :: "r"(s), "l"(g));
}
__device__ __forceinline__ void cpa_commit() {
    asm volatile("cp.async.commit_group;" ::: "memory");
}
__device__ __forceinline__ void mma16816(float* c, const uint32_t* a, const uint32_t* b) {
    asm volatile(
        "mma.sync.aligned.m16n8k16.row.col.f32.bf16.bf16.f32 "
        "{%0,%1,%2,%3}, {%4,%5,%6,%7}, {%8,%9}, {%0,%1,%2,%3};"
        : "+f"(c[0]), "+f"(c[1]), "+f"(c[2]), "+f"(c[3])
        : "r"(a[0]), "r"(a[1]), "r"(a[2]), "r"(a[3]), "r"(b[0]), "r"(b[1]));
}

// ---------------- shared GEMM core ------------------------------------------
// Block: 128x128 C, 256 threads. Warp w: wm = w&1 (64 rows), wn = w>>1 (32 cols).
// Accum: acc[mi][nj][4]; fragments per PTX m16n8k16 bf16 layout.
struct GemmSmem {
    __align__(16) __nv_bfloat16 A[2][128 * SMS];
    __align__(16) __nv_bfloat16 B[2][128 * SMS];
};

__device__ __forceinline__ void issue_tile(uint32_t sa, uint32_t sb,
                                           const __nv_bfloat16* __restrict__ A3, int lda3,
                                           const __nv_bfloat16* __restrict__ B3, int ldb3,
                                           int k0, int tid) {
#pragma unroll
    for (int i = 0; i < 2; i++) {
        int idx = i * 256 + tid;
        int r = idx >> 2, c = idx & 3;
        cpa16(sa + (r * SMS + c * 8) * 2, A3 + (size_t)r * lda3 + k0 + c * 8);
    }
#pragma unroll
    for (int i = 0; i < 2; i++) {
        int idx = i * 256 + tid;
        int r = idx >> 2, c = idx & 3;
        cpa16(sb + (r * SMS + c * 8) * 2, B3 + (size_t)r * ldb3 + k0 + c * 8);
    }
    cpa_commit();
}

__device__ __forceinline__ void gemm_main(const __nv_bfloat16* __restrict__ A3, int lda3,
                                          const __nv_bfloat16* __restrict__ B3, int ldb3,
                                          int nchunks, GemmSmem* sm, float (&acc)[4][4][4]) {
    int tid = threadIdx.x, wid = tid >> 5, lane = tid & 31;
    int wm = (wid & 1) * 64, wn = (wid >> 1) * 32;
    int g = lane >> 2, t = lane & 3;
    uint32_t sa0 = s2u(sm->A[0]), sb0 = s2u(sm->B[0]);
    uint32_t sa1 = s2u(sm->A[1]), sb1 = s2u(sm->B[1]);

    issue_tile(sa0, sb0, A3, lda3, B3, ldb3, 0, tid);

    for (int c = 0; c < nchunks; c++) {
        int b = c & 1;
        if (c + 1 < nchunks) {
            issue_tile(b ? sa0 : sa1, b ? sb0 : sb1, A3, lda3, B3, ldb3, (c + 1) * BK, tid);
            asm volatile("cp.async.wait_group 1;" ::: "memory");
        } else {
            asm volatile("cp.async.wait_group 0;" ::: "memory");
        }
        __syncthreads();
        const __nv_bfloat16* As = sm->A[b];
        const __nv_bfloat16* Bs = sm->B[b];
#pragma unroll
        for (int ks = 0; ks < BK; ks += 16) {
            uint32_t af[4][4], bf[4][2];
#pragma unroll
            for (int mi = 0; mi < 4; mi++) {
                int r0 = wm + mi * 16 + g;
                af[mi][0] = *(const uint32_t*)(As + r0 * SMS + ks + 2 * t);
                af[mi][1] = *(const uint32_t*)(As + (r0 + 8) * SMS + ks + 2 * t);
                af[mi][2] = *(const uint32_t*)(As + r0 * SMS + ks + 2 * t + 8);
                af[mi][3] = *(const uint32_t*)(As + (r0 + 8) * SMS + ks + 2 * t + 8);
            }
#pragma unroll
            for (int nj = 0; nj < 4; nj++) {
                int n0 = wn + nj * 8 + g;
                bf[nj][0] = *(const uint32_t*)(Bs + n0 * SMS + ks + 2 * t);
                bf[nj][1] = *(const uint32_t*)(Bs + n0 * SMS + ks + 2 * t + 8);
            }
#pragma unroll
            for (int mi = 0; mi < 4; mi++)
#pragma unroll
                for (int nj = 0; nj < 4; nj++)
                    mma16816(acc[mi][nj], af[mi], bf[nj]);
        }
        __syncthreads();
    }
}

// ---------------- GEMM -> fp32 C  (QKV + WO) --------------------------------
__global__ __launch_bounds__(256) void gemm3_f32(const __nv_bfloat16* __restrict__ A3, int lda3,
                                                 const __nv_bfloat16* __restrict__ B3, int ldb3,
                                                 float* __restrict__ C, int ldc, int nchunks) {
    __shared__ GemmSmem sm;
    float acc[4][4][4] = {};
    gemm_main(A3 + (size_t)blockIdx.x * 128 * lda3, lda3,
              B3 + (size_t)blockIdx.y * 128 * ldb3, ldb3, nchunks, &sm, acc);
    int tid = threadIdx.x, wid = tid >> 5, lane = tid & 31;
    int wm = (wid & 1) * 64, wn = (wid >> 1) * 32;
    int g = lane >> 2, t = lane & 3;
#pragma unroll
    for (int mi = 0; mi < 4; mi++)
#pragma unroll
        for (int nj = 0; nj < 4; nj++) {
            int r0 = blockIdx.x * 128 + wm + mi * 16 + g;
            int c0 = blockIdx.y * 128 + wn + nj * 8 + t * 2;
            *(float2*)(C + (size_t)r0 * ldc + c0)       = make_float2(acc[mi][nj][0], acc[mi][nj][1]);
            *(float2*)(C + (size_t)(r0 + 8) * ldc + c0) = make_float2(acc[mi][nj][2], acc[mi][nj][3]);
        }
}

// ---------------- scores = scale*QK^T, causal-masked, fp32 ------------------
__global__ __launch_bounds__(256) void score3(const __nv_bfloat16* __restrict__ Q3,
                                              const __nv_bfloat16* __restrict__ K3,
                                              float* __restrict__ S) {
    int bx = blockIdx.x, by = blockIdx.y;
    if (by > bx) return;
    int h = blockIdx.z;
    __shared__ GemmSmem sm;
    float acc[4][4][4] = {};
    gemm_main(Q3 + (size_t)bx * 128 * K3DIM + h * K3HD, K3DIM,
              K3 + (size_t)by * 128 * (NKV * K3HD) + (h >> 2) * K3HD, NKV * K3HD,
              K3HD / BK, &sm, acc);
    int tid = threadIdx.x, wid = tid >> 5, lane = tid & 31;
    int wm = (wid & 1) * 64, wn = (wid >> 1) * 32;
    int g = lane >> 2, t = lane & 3;
    const float scale = 0.088388347648318447f;
    bool diag = (bx == by);
#pragma unroll
    for (int mi = 0; mi < 4; mi++)
#pragma unroll
        for (int nj = 0; nj < 4; nj++) {
            int rl0 = wm + mi * 16 + g;
            int cl0 = wn + nj * 8 + t * 2;
#pragma unroll
            for (int half = 0; half < 2; half++) {
                int qrow = bx * 128 + rl0 + half * 8;
                int kcol = by * 128 + cl0;
                float v0 = acc[mi][nj][2 * half]     * scale;
                float v1 = acc[mi][nj][2 * half + 1] * scale;
                if (diag) {
                    if (kcol     > qrow) v0 = -CUDART_INF_F;
                    if (kcol + 1 > qrow) v1 = -CUDART_INF_F;
                }
                *(float2*)(S + ((size_t)h * S_LEN + qrow) * S_LEN + kcol) = make_float2(v0, v1);
            }
        }
}

// ---------------- PV: out_h = P @ V, epilogue writes tripled AT3 ------------
__global__ __launch_bounds__(256) void pv3(const __nv_bfloat16* __restrict__ P3,
                                           const __nv_bfloat16* __restrict__ Vt3,
                                           __nv_bfloat16* __restrict__ AT3) {
    int tt = blockIdx.x, h = blockIdx.y;
    __shared__ GemmSmem sm;
    float acc[4][4][4] = {};
    gemm_main(P3 + ((size_t)h * S_LEN + (size_t)tt * 128) * K3S, K3S,
              Vt3 + (size_t)(h >> 2) * 128 * K3S, K3S, 12 * (tt + 1), &sm, acc);
    int tid = threadIdx.x, wid = tid >> 5, lane = tid & 31;
    int wm = (wid & 1) * 64, wn = (wid >> 1) * 32;
    int g = lane >> 2, t = lane & 3;
#pragma unroll
    for (int mi = 0; mi < 4; mi++)
#pragma unroll
        for (int nj = 0; nj < 4; nj++) {
            int cl = wn + nj * 8 + t * 2;                 // 0..126 within head
            int k = h * 128 + cl;                          // global output dim
            size_t kb = (size_t)(k >> 6) * 192 + (k & 63);
#pragma unroll
            for (int half = 0; half < 2; half++) {
                int row = tt * 128 + wm + mi * 16 + g + half * 8;
                __nv_bfloat16 h0, l0, h1, l1;
                split2(acc[mi][nj][2 * half], h0, l0);
                split2(acc[mi][nj][2 * half + 1], h1, l1);
                __nv_bfloat162 hp; hp.x = h0; hp.y = h1;
                __nv_bfloat162 lp; lp.x = l0; lp.y = l1;
                __nv_bfloat16* base = AT3 + (size_t)row * K3DIM + kb;
                *(__nv_bfloat162*)(base)       = hp;       // A-pattern: hi, lo, hi
                *(__nv_bfloat162*)(base + 64)  = lp;
                *(__nv_bfloat162*)(base + 128) = hp;
            }
        }
}

// ---------------- conversion kernels ----------------------------------------
// A-pattern: [hi, lo, hi]   B-pattern: [hi, hi, lo]   (per 64-elem K block)
__global__ void conv_a3(const float* __restrict__ W, __nv_bfloat16* __restrict__ W3, int total) {
    int idx = blockIdx.x * 256 + threadIdx.x;
    if (idx >= total) return;
    int k = idx & 4095, m = idx >> 12;
    __nv_bfloat16 hi, lo;
    split2(W[idx], hi, lo);
    size_t base = (size_t)m * K3DIM + (size_t)(k >> 6) * 192 + (k & 63);
    W3[base] = hi; W3[base + 64] = lo; W3[base + 128] = hi;
}
__global__ void conv_b3(const float* __restrict__ W, __nv_bfloat16* __restrict__ W3, int total) {
    int idx = blockIdx.x * 256 + threadIdx.x;
    if (idx >= total) return;
    int k = idx & 4095, m = idx >> 12;
    __nv_bfloat16 hi, lo;
    split2(W[idx], hi, lo);
    size_t base = (size_t)m * K3DIM + (size_t)(k >> 6) * 192 + (k & 63);
    W3[base] = hi; W3[base + 64] = hi; W3[base + 128] = lo;
}

__global__ void rope_conv_q(const float* __restrict__ Q, const float* __restrict__ fc,
                            const float* __restrict__ fs, __nv_bfloat16* __restrict__ Q3) {
    int idx = blockIdx.x * 256 + threadIdx.x;           // S*NH*64
    int i = idx & 63, h = (idx >> 6) & 31, s = idx >> 11;
    float c = fc[(s << 6) + i], sn = fs[(s << 6) + i];
    const float* qp = Q + (size_t)s * DIM + h * HD + 2 * i;
    float xr = qp[0], xi = qp[1];
    float vr = xr * c - xi * sn, vi = xr * sn + xi * c;
    int d0 = 2 * i;
    size_t base = (size_t)s * K3DIM + h * K3HD + (size_t)(d0 >> 6) * 192 + (d0 & 63);
    __nv_bfloat16 hr, lr, hi_, li;
    split2(vr, hr, lr); split2(vi, hi_, li);
    __nv_bfloat162 hp; hp.x = hr; hp.y = hi_;
    __nv_bfloat162 lp; lp.x = lr; lp.y = li;
    *(__nv_bfloat162*)(Q3 + base)       = hp;  // A-pattern
    *(__nv_bfloat162*)(Q3 + base + 64)  = lp;
    *(__nv_bfloat162*)(Q3 + base + 128) = hp;
}
__global__ void rope_conv_k(const float* __restrict__ K, const float* __restrict__ fc,
                            const float* __restrict__ fs, __nv_bfloat16* __restrict__ K3) {
    int idx = blockIdx.x * 256 + threadIdx.x;           // S*NKV*64
    int i = idx & 63, h = (idx >> 6) & 7, s = idx >> 9;
    float c = fc[(s << 6) + i], sn = fs[(s << 6) + i];
    const float* kp = K + (size_t)s * KV_DIM + h * HD + 2 * i;
    float xr = kp[0], xi = kp[1];
    float vr = xr * c - xi * sn, vi = xr * sn + xi * c;
    int d0 = 2 * i;
    size_t base = (size_t)s * (NKV * K3HD) + h * K3HD + (size_t)(d0 >> 6) * 192 + (d0 & 63);
    __nv_bfloat16 hr, lr, hi_, li;
    split2(vr, hr, lr); split2(vi, hi_, li);
    __nv_bfloat162 hp; hp.x = hr; hp.y = hi_;
    __nv_bfloat162 lp; lp.x = lr; lp.y = li;
    *(__nv_bfloat162*)(K3 + base)       = hp;  // B-pattern
    *(__nv_bfloat162*)(K3 + base + 64)  = hp;
    *(__nv_bfloat162*)(K3 + base + 128) = lp;
}

// V [S][KV_DIM] -> Vt3 [d=1024][3*2048] B-pattern (smem transpose)
__global__ void conv_vt(const float* __restrict__ V, __nv_bfloat16* __restrict__ Vt3) {
    __shared__ float t[32][33];
    int s0 = blockIdx.x * 32, d0 = blockIdx.y * 32;
    int tx = threadIdx.x, ty = threadIdx.y;
#pragma unroll
    for (int i = 0; i < 32; i += 8)
        t[ty + i][tx] = V[(size_t)(s0 + ty + i) * KV_DIM + d0 + tx];
    __syncthreads();
#pragma unroll
    for (int i = 0; i < 32; i += 8) {
        int d = d0 + ty + i, s = s0 + tx;
        __nv_bfloat16 hi, lo;
        split2(t[tx][ty + i], hi, lo);
        size_t base = (size_t)d * K3S + (size_t)(s >> 6) * 192 + (s & 63);
        Vt3[base] = hi; Vt3[base + 64] = hi; Vt3[base + 128] = lo;
    }
}

// ---------------- FFMA-only exp + fused softmax -> tripled P3 ---------------
__device__ __forceinline__ float fexp(float x) {
    float y = fmaxf(x * 1.4426950408889634f, -126.0f);
    float fl = floorf(y);
    float f = y - fl;
    float p = 1.5403530e-4f;
    p = fmaf(p, f, 1.3333558e-3f);
    p = fmaf(p, f, 9.6181291e-3f);
    p = fmaf(p, f, 5.5504109e-2f);
    p = fmaf(p, f, 2.4022651e-1f);
    p = fmaf(p, f, 6.9314718e-1f);
    p = fmaf(p, f, 1.0f);
    int e = (int)fl;
    return __int_as_float((e + 127) << 23) * p;
}

__global__ __launch_bounds__(128) void softmax_p3(const float* __restrict__ Sb,
                                                  __nv_bfloat16* __restrict__ P3) {
    int q = blockIdx.x, h = blockIdx.y;
    int n = (q >> 7) + 1;
    const float* row = Sb + ((size_t)h * S_LEN + q) * S_LEN;
    __nv_bfloat16* prow = P3 + ((size_t)h * S_LEN + q) * K3S;
    int tid = threadIdx.x;
    float v[16];
    float m = -CUDART_INF_F;
    for (int c = 0; c < n; c++) { v[c] = row[(c << 7) + tid]; m = fmaxf(m, v[c]); }
#pragma unroll
    for (int o = 16; o; o >>= 1) m = fmaxf(m, __shfl_xor_sync(~0u, m, o));
    __shared__ float red[4];
    if ((tid & 31) == 0) red[tid >> 5] = m;
    __syncthreads();
    m = fmaxf(fmaxf(red[0], red[1]), fmaxf(red[2], red[3]));
    __syncthreads();
    float s = 0.f;
    for (int c = 0; c < n; c++) { v[c] = fexp(v[c] - m); s += v[c]; }
#pragma unroll
    for (int o = 16; o; o >>= 1) s += __shfl_xor_sync(~0u, s, o);
    if ((tid & 31) == 0) red[tid >> 5] = s;
    __syncthreads();
    s = red[0] + red[1] + red[2] + red[3];
    float inv = __fdividef(1.0f, s);
    for (int c = 0; c < n; c++) {
        float p = v[c] * inv;
        int si = (c << 7) + tid;
        __nv_bfloat16 hi, lo;
        split2(p, hi, lo);
        size_t base = (size_t)(si >> 6) * 192 + (si & 63);
        prow[base] = hi; prow[base + 64] = lo; prow[base + 128] = hi;  // A-pattern
    }
}

// ---------------- launch ----------------------------------------------------
extern "C" void kernel_launch(void* const* d_in, const int* in_sizes, int n_in,
                              void* d_out, int out_size) {
    const float* x  = (const float*)d_in[0];
    const float* wq = (const float*)d_in[1];
    const float* wk = (const float*)d_in[2];
    const float* wv = (const float*)d_in[3];
    const float* wo = (const float*)d_in[4];
    const float* fc = (const float*)d_in[5];
    const float* fs = (const float*)d_in[6];
    float* out = (float*)d_out;

    float *Q, *K, *V, *S;
    __nv_bfloat16 *x3, *wq3, *wk3, *wv3, *wo3, *q3, *k3, *vt3, *p3, *at3;
    cudaGetSymbolAddress((void**)&Q,   g_q);
    cudaGetSymbolAddress((void**)&K,   g_k);
    cudaGetSymbolAddress((void**)&V,   g_v);
    cudaGetSymbolAddress((void**)&S,   g_s);
    cudaGetSymbolAddress((void**)&x3,  g_x3);
    cudaGetSymbolAddress((void**)&wq3, g_wq3);
    cudaGetSymbolAddress((void**)&wk3, g_wk3);
    cudaGetSymbolAddress((void**)&wv3, g_wv3);
    cudaGetSymbolAddress((void**)&wo3, g_wo3);
    cudaGetSymbolAddress((void**)&q3,  g_q3);
    cudaGetSymbolAddress((void**)&k3,  g_k3);
    cudaGetSymbolAddress((void**)&vt3, g_vt3);
    cudaGetSymbolAddress((void**)&p3,  g_p3);
    cudaGetSymbolAddress((void**)&at3, g_at3);

    // operand splitting (bf16 hi/lo, K-tripled)
    conv_a3<<<(S_LEN * DIM + 255) / 256, 256>>>(x,  x3,  S_LEN * DIM);
    conv_b3<<<(DIM * DIM + 255) / 256, 256>>>(wq, wq3, DIM * DIM);
    conv_b3<<<(KV_DIM * DIM + 255) / 256, 256>>>(wk, wk3, KV_DIM * DIM);
    conv_b3<<<(KV_DIM * DIM + 255) / 256, 256>>>(wv, wv3, KV_DIM * DIM);
    conv_b3<<<(DIM * DIM + 255) / 256, 256>>>(wo, wo3, DIM * DIM);

    // QKV projections (tensor cores via mma.sync)
    gemm3_f32<<<dim3(16, 32), 256>>>(x3, K3DIM, wq3, K3DIM, Q, DIM,    K3DIM / BK);
    gemm3_f32<<<dim3(16,  8), 256>>>(x3, K3DIM, wk3, K3DIM, K, KV_DIM, K3DIM / BK);
    gemm3_f32<<<dim3(16,  8), 256>>>(x3, K3DIM, wv3, K3DIM, V, KV_DIM, K3DIM / BK);

    // RoPE + split (fused)
    rope_conv_q<<<(S_LEN * NH  * 64) / 256, 256>>>(Q, fc, fs, q3);
    rope_conv_k<<<(S_LEN * NKV * 64) / 256, 256>>>(K, fc, fs, k3);
    conv_vt<<<dim3(S_LEN / 32, KV_DIM / 32), dim3(32, 8)>>>(V, vt3);

    // attention
    score3<<<dim3(16, 16, NH), 256>>>(q3, k3, S);
    softmax_p3<<<dim3(S_LEN, NH), 128>>>(S, p3);
    pv3<<<dim3(16, NH), 256>>>(p3, vt3, at3);

    // output projection
    gemm3_f32<<<dim3(16, 32), 256>>>(at3, K3DIM, wo3, K3DIM, out, DIM, K3DIM / BK);
}

// round 10
// speedup vs baseline: 2.0290x; 1.0734x over previous
#include <cuda_runtime.h>
#include <cuda_bf16.h>
#include <math_constants.h>
#include <cstdint>

#define S_LEN  2048
#define DIM    4096
#define KV_DIM 1024
#define NH     32
#define NKV    8
#define HD     128
#define K3DIM  12288      // 3*4096 (tripled K for projections)
#define K3HD   384        // 3*128  (tripled K for scores)
#define K3S    6144       // 3*2048 (tripled K for PV)
#define BK     32
#define SMS    40         // smem row stride in bf16 (32 + 8 pad; 80B, 16B-aligned)

// ---------------- scratch (module-load allocated) ---------------------------
__device__ __align__(16) float g_q[S_LEN * DIM];
__device__ __align__(16) float g_k[S_LEN * KV_DIM];
__device__ __align__(16) float g_v[S_LEN * KV_DIM];
__device__ __align__(16) float g_s[(size_t)NH * S_LEN * S_LEN];          // fp32 scores
__device__ __align__(16) __nv_bfloat16 g_x3 [S_LEN * K3DIM];
__device__ __align__(16) __nv_bfloat16 g_wq3[DIM * K3DIM];
__device__ __align__(16) __nv_bfloat16 g_wk3[KV_DIM * K3DIM];
__device__ __align__(16) __nv_bfloat16 g_wv3[KV_DIM * K3DIM];
__device__ __align__(16) __nv_bfloat16 g_wo3[DIM * K3DIM];
__device__ __align__(16) __nv_bfloat16 g_q3 [S_LEN * K3DIM];             // roped, A-pat
__device__ __align__(16) __nv_bfloat16 g_k3 [S_LEN * (NKV * K3HD)];      // roped, B-pat
__device__ __align__(16) __nv_bfloat16 g_vt3[KV_DIM * K3S];              // V^T, B-pat
__device__ __align__(16) __nv_bfloat16 g_p3 [(size_t)NH * S_LEN * K3S];  // probs, A-pat
__device__ __align__(16) __nv_bfloat16 g_at3[S_LEN * K3DIM];             // attn out, A-pat

// ---------------- helpers ----------------------------------------------------
__device__ __forceinline__ void split2(float a, __nv_bfloat16& hi, __nv_bfloat16& lo) {
    hi = __float2bfloat16(a);
    lo = __float2bfloat16(a - __bfloat162float(hi));
}
__device__ __forceinline__ uint32_t s2u(const void* p) {
    uint32_t a;
    asm("{ .reg .u64 t; cvta.to.shared.u64 t, %1; cvt.u32.u64 %0, t; }" : "=r"(a) : "l"(p));
    return a;
}
__device__ __forceinline__ void cpa16(uint32_t s, const void* g) {
    asm volatile("cp.async.cg.shared.global [%0], [%1], 16;" :: "r"(s), "l"(g));
}
__device__ __forceinline__ void cpa_commit() {
    asm volatile("cp.async.commit_group;" ::: "memory");
}
__device__ __forceinline__ void mma16816(float* c, const uint32_t* a, const uint32_t* b) {
    asm volatile(
        "mma.sync.aligned.m16n8k16.row.col.f32.bf16.bf16.f32 "
        "{%0,%1,%2,%3}, {%4,%5,%6,%7}, {%8,%9}, {%0,%1,%2,%3};"
        : "+f"(c[0]), "+f"(c[1]), "+f"(c[2]), "+f"(c[3])
        : "r"(a[0]), "r"(a[1]), "r"(a[2]), "r"(a[3]), "r"(b[0]), "r"(b[1]));
}
__device__ __forceinline__ void ldsm4(uint32_t& r0, uint32_t& r1, uint32_t& r2, uint32_t& r3,
                                      uint32_t addr) {
    asm volatile("ldmatrix.sync.aligned.m8n8.x4.shared.b16 {%0,%1,%2,%3}, [%4];"
                 : "=r"(r0), "=r"(r1), "=r"(r2), "=r"(r3) : "r"(addr));
}

// ---------------- shared GEMM core ------------------------------------------
// Block: 128x128 C, 256 threads. Warp w: wm = w&1 (64 rows), wn = w>>1 (32 cols).
struct GemmSmem {
    __align__(16) __nv_bfloat16 A[2][128 * SMS];
    __align__(16) __nv_bfloat16 B[2][128 * SMS];
};

__device__ __forceinline__ void issue_tile(uint32_t sa, uint32_t sb,
                                           const __nv_bfloat16* __restrict__ A3, int lda3,
                                           const __nv_bfloat16* __restrict__ B3, int ldb3,
                                           int k0, int tid) {
#pragma unroll
    for (int i = 0; i < 2; i++) {
        int idx = i * 256 + tid;
        int r = idx >> 2, c = idx & 3;
        cpa16(sa + (r * SMS + c * 8) * 2, A3 + (size_t)r * lda3 + k0 + c * 8);
    }
#pragma unroll
    for (int i = 0; i < 2; i++) {
        int idx = i * 256 + tid;
        int r = idx >> 2, c = idx & 3;
        cpa16(sb + (r * SMS + c * 8) * 2, B3 + (size_t)r * ldb3 + k0 + c * 8);
    }
    cpa_commit();
}

__device__ __forceinline__ void gemm_main(const __nv_bfloat16* __restrict__ A3, int lda3,
                                          const __nv_bfloat16* __restrict__ B3, int ldb3,
                                          int nchunks, GemmSmem* sm, float (&acc)[4][4][4]) {
    int tid = threadIdx.x, wid = tid >> 5, lane = tid & 31;
    int wm = (wid & 1) * 64, wn = (wid >> 1) * 32;
    uint32_t sa0 = s2u(sm->A[0]), sb0 = s2u(sm->B[0]);
    uint32_t sa1 = s2u(sm->A[1]), sb1 = s2u(sm->B[1]);

    // ldmatrix per-lane row addressing (byte offsets within a buffer)
    int a_row = wm + (lane & 15);                 // rows m..m+15, lanes 16-31 -> k+8
    int a_kh  = (lane >> 4) * 8;
    int b_row = wn + (lane & 7) + ((lane >> 4) ? 8 : 0);  // packs nj and nj+1 tiles
    int b_kh  = ((lane >> 3) & 1) * 8;
    uint32_t a_off = (uint32_t)(a_row * SMS + a_kh) * 2;
    uint32_t b_off = (uint32_t)(b_row * SMS + b_kh) * 2;

    issue_tile(sa0, sb0, A3, lda3, B3, ldb3, 0, tid);

    for (int c = 0; c < nchunks; c++) {
        int b = c & 1;
        if (c + 1 < nchunks) {
            issue_tile(b ? sa0 : sa1, b ? sb0 : sb1, A3, lda3, B3, ldb3, (c + 1) * BK, tid);
            asm volatile("cp.async.wait_group 1;" ::: "memory");
        } else {
            asm volatile("cp.async.wait_group 0;" ::: "memory");
        }
        __syncthreads();
        uint32_t As_u = (b ? sa1 : sa0);
        uint32_t Bs_u = (b ? sb1 : sb0);
#pragma unroll
        for (int ks = 0; ks < BK; ks += 16) {
            uint32_t af[4][4], bf[4][2];
            uint32_t aa = As_u + a_off + ks * 2;
            uint32_t ba = Bs_u + b_off + ks * 2;
#pragma unroll
            for (int mi = 0; mi < 4; mi++)
                ldsm4(af[mi][0], af[mi][1], af[mi][2], af[mi][3],
                      aa + mi * 16 * SMS * 2);
#pragma unroll
            for (int njp = 0; njp < 2; njp++)
                ldsm4(bf[2 * njp][0], bf[2 * njp][1], bf[2 * njp + 1][0], bf[2 * njp + 1][1],
                      ba + njp * 16 * SMS * 2);
#pragma unroll
            for (int mi = 0; mi < 4; mi++)
#pragma unroll
                for (int nj = 0; nj < 4; nj++)
                    mma16816(acc[mi][nj], af[mi], bf[nj]);
        }
        __syncthreads();
    }
}

// ---------------- GEMM -> fp32 C  (QKV + WO) --------------------------------
__global__ __launch_bounds__(256) void gemm3_f32(const __nv_bfloat16* __restrict__ A3, int lda3,
                                                 const __nv_bfloat16* __restrict__ B3, int ldb3,
                                                 float* __restrict__ C, int ldc, int nchunks) {
    __shared__ GemmSmem sm;
    float acc[4][4][4] = {};
    gemm_main(A3 + (size_t)blockIdx.x * 128 * lda3, lda3,
              B3 + (size_t)blockIdx.y * 128 * ldb3, ldb3, nchunks, &sm, acc);
    int tid = threadIdx.x, wid = tid >> 5, lane = tid & 31;
    int wm = (wid & 1) * 64, wn = (wid >> 1) * 32;
    int g = lane >> 2, t = lane & 3;
#pragma unroll
    for (int mi = 0; mi < 4; mi++)
#pragma unroll
        for (int nj = 0; nj < 4; nj++) {
            int r0 = blockIdx.x * 128 + wm + mi * 16 + g;
            int c0 = blockIdx.y * 128 + wn + nj * 8 + t * 2;
            *(float2*)(C + (size_t)r0 * ldc + c0)       = make_float2(acc[mi][nj][0], acc[mi][nj][1]);
            *(float2*)(C + (size_t)(r0 + 8) * ldc + c0) = make_float2(acc[mi][nj][2], acc[mi][nj][3]);
        }
}

// ---------------- scores = scale*QK^T, causal, compact triangular grid ------
__global__ __launch_bounds__(256) void score3(const __nv_bfloat16* __restrict__ Q3,
                                              const __nv_bfloat16* __restrict__ K3,
                                              float* __restrict__ S) {
    int li = blockIdx.x;                       // 0..135 lower-triangle tiles
    int bx = (int)((sqrtf(8.f * li + 1.f) - 1.f) * 0.5f);
    while ((bx + 1) * (bx + 2) / 2 <= li) bx++;
    while (bx * (bx + 1) / 2 > li) bx--;
    int by = li - bx * (bx + 1) / 2;
    int h = blockIdx.y;
    __shared__ GemmSmem sm;
    float acc[4][4][4] = {};
    gemm_main(Q3 + (size_t)bx * 128 * K3DIM + h * K3HD, K3DIM,
              K3 + (size_t)by * 128 * (NKV * K3HD) + (h >> 2) * K3HD, NKV * K3HD,
              K3HD / BK, &sm, acc);
    int tid = threadIdx.x, wid = tid >> 5, lane = tid & 31;
    int wm = (wid & 1) * 64, wn = (wid >> 1) * 32;
    int g = lane >> 2, t = lane & 3;
    const float scale = 0.088388347648318447f;
    bool diag = (bx == by);
#pragma unroll
    for (int mi = 0; mi < 4; mi++)
#pragma unroll
        for (int nj = 0; nj < 4; nj++) {
            int rl0 = wm + mi * 16 + g;
            int cl0 = wn + nj * 8 + t * 2;
#pragma unroll
            for (int half = 0; half < 2; half++) {
                int qrow = bx * 128 + rl0 + half * 8;
                int kcol = by * 128 + cl0;
                float v0 = acc[mi][nj][2 * half]     * scale;
                float v1 = acc[mi][nj][2 * half + 1] * scale;
                if (diag) {
                    if (kcol     > qrow) v0 = -CUDART_INF_F;
                    if (kcol + 1 > qrow) v1 = -CUDART_INF_F;
                }
                *(float2*)(S + ((size_t)h * S_LEN + qrow) * S_LEN + kcol) = make_float2(v0, v1);
            }
        }
}

// ---------------- PV: out_h = P @ V (longest tiles first) -------------------
__global__ __launch_bounds__(256) void pv3(const __nv_bfloat16* __restrict__ P3,
                                           const __nv_bfloat16* __restrict__ Vt3,
                                           __nv_bfloat16* __restrict__ AT3) {
    int tt = 15 - blockIdx.x, h = blockIdx.y;
    __shared__ GemmSmem sm;
    float acc[4][4][4] = {};
    gemm_main(P3 + ((size_t)h * S_LEN + (size_t)tt * 128) * K3S, K3S,
              Vt3 + (size_t)(h >> 2) * 128 * K3S, K3S, 12 * (tt + 1), &sm, acc);
    int tid = threadIdx.x, wid = tid >> 5, lane = tid & 31;
    int wm = (wid & 1) * 64, wn = (wid >> 1) * 32;
    int g = lane >> 2, t = lane & 3;
#pragma unroll
    for (int mi = 0; mi < 4; mi++)
#pragma unroll
        for (int nj = 0; nj < 4; nj++) {
            int cl = wn + nj * 8 + t * 2;                 // 0..126 within head
            int k = h * 128 + cl;                          // global output dim
            size_t kb = (size_t)(k >> 6) * 192 + (k & 63);
#pragma unroll
            for (int half = 0; half < 2; half++) {
                int row = tt * 128 + wm + mi * 16 + g + half * 8;
                __nv_bfloat16 h0, l0, h1, l1;
                split2(acc[mi][nj][2 * half], h0, l0);
                split2(acc[mi][nj][2 * half + 1], h1, l1);
                __nv_bfloat162 hp; hp.x = h0; hp.y = h1;
                __nv_bfloat162 lp; lp.x = l0; lp.y = l1;
                __nv_bfloat16* base = AT3 + (size_t)row * K3DIM + kb;
                *(__nv_bfloat162*)(base)       = hp;       // A-pattern: hi, lo, hi
                *(__nv_bfloat162*)(base + 64)  = lp;
                *(__nv_bfloat162*)(base + 128) = hp;
            }
        }
}

// ---------------- conversion kernels (float2-vectorized) --------------------
// A-pattern: [hi, lo, hi]   B-pattern: [hi, hi, lo]   (per 64-elem K block)
__global__ void conv_a3(const float* __restrict__ W, __nv_bfloat16* __restrict__ W3, int total2) {
    int idx = blockIdx.x * 256 + threadIdx.x;        // pairs
    if (idx >= total2) return;
    int k = (idx & 2047) * 2, m = idx >> 11;
    float2 w = *(const float2*)(W + (size_t)m * 4096 + k);
    __nv_bfloat16 h0, l0, h1, l1;
    split2(w.x, h0, l0); split2(w.y, h1, l1);
    __nv_bfloat162 hp; hp.x = h0; hp.y = h1;
    __nv_bfloat162 lp; lp.x = l0; lp.y = l1;
    size_t base = (size_t)m * K3DIM + (size_t)(k >> 6) * 192 + (k & 63);
    *(__nv_bfloat162*)(W3 + base)       = hp;
    *(__nv_bfloat162*)(W3 + base + 64)  = lp;
    *(__nv_bfloat162*)(W3 + base + 128) = hp;
}
__global__ void conv_b3(const float* __restrict__ W, __nv_bfloat16* __restrict__ W3, int total2) {
    int idx = blockIdx.x * 256 + threadIdx.x;        // pairs
    if (idx >= total2) return;
    int k = (idx & 2047) * 2, m = idx >> 11;
    float2 w = *(const float2*)(W + (size_t)m * 4096 + k);
    __nv_bfloat16 h0, l0, h1, l1;
    split2(w.x, h0, l0); split2(w.y, h1, l1);
    __nv_bfloat162 hp; hp.x = h0; hp.y = h1;
    __nv_bfloat162 lp; lp.x = l0; lp.y = l1;
    size_t base = (size_t)m * K3DIM + (size_t)(k >> 6) * 192 + (k & 63);
    *(__nv_bfloat162*)(W3 + base)       = hp;
    *(__nv_bfloat162*)(W3 + base + 64)  = hp;
    *(__nv_bfloat162*)(W3 + base + 128) = lp;
}

__global__ void rope_conv_q(const float* __restrict__ Q, const float* __restrict__ fc,
                            const float* __restrict__ fs, __nv_bfloat16* __restrict__ Q3) {
    int idx = blockIdx.x * 256 + threadIdx.x;           // S*NH*64
    int i = idx & 63, h = (idx >> 6) & 31, s = idx >> 11;
    float c = fc[(s << 6) + i], sn = fs[(s << 6) + i];
    const float* qp = Q + (size_t)s * DIM + h * HD + 2 * i;
    float xr = qp[0], xi = qp[1];
    float vr = xr * c - xi * sn, vi = xr * sn + xi * c;
    int d0 = 2 * i;
    size_t base = (size_t)s * K3DIM + h * K3HD + (size_t)(d0 >> 6) * 192 + (d0 & 63);
    __nv_bfloat16 hr, lr, hi_, li;
    split2(vr, hr, lr); split2(vi, hi_, li);
    __nv_bfloat162 hp; hp.x = hr; hp.y = hi_;
    __nv_bfloat162 lp; lp.x = lr; lp.y = li;
    *(__nv_bfloat162*)(Q3 + base)       = hp;  // A-pattern
    *(__nv_bfloat162*)(Q3 + base + 64)  = lp;
    *(__nv_bfloat162*)(Q3 + base + 128) = hp;
}
__global__ void rope_conv_k(const float* __restrict__ K, const float* __restrict__ fc,
                            const float* __restrict__ fs, __nv_bfloat16* __restrict__ K3) {
    int idx = blockIdx.x * 256 + threadIdx.x;           // S*NKV*64
    int i = idx & 63, h = (idx >> 6) & 7, s = idx >> 9;
    float c = fc[(s << 6) + i], sn = fs[(s << 6) + i];
    const float* kp = K + (size_t)s * KV_DIM + h * HD + 2 * i;
    float xr = kp[0], xi = kp[1];
    float vr = xr * c - xi * sn, vi = xr * sn + xi * c;
    int d0 = 2 * i;
    size_t base = (size_t)s * (NKV * K3HD) + h * K3HD + (size_t)(d0 >> 6) * 192 + (d0 & 63);
    __nv_bfloat16 hr, lr, hi_, li;
    split2(vr, hr, lr); split2(vi, hi_, li);
    __nv_bfloat162 hp; hp.x = hr; hp.y = hi_;
    __nv_bfloat162 lp; lp.x = lr; lp.y = li;
    *(__nv_bfloat162*)(K3 + base)       = hp;  // B-pattern
    *(__nv_bfloat162*)(K3 + base + 64)  = hp;
    *(__nv_bfloat162*)(K3 + base + 128) = lp;
}

// V [S][KV_DIM] -> Vt3 [d=1024][3*2048] B-pattern (smem transpose)
__global__ void conv_vt(const float* __restrict__ V, __nv_bfloat16* __restrict__ Vt3) {
    __shared__ float t[32][33];
    int s0 = blockIdx.x * 32, d0 = blockIdx.y * 32;
    int tx = threadIdx.x, ty = threadIdx.y;
#pragma unroll
    for (int i = 0; i < 32; i += 8)
        t[ty + i][tx] = V[(size_t)(s0 + ty + i) * KV_DIM + d0 + tx];
    __syncthreads();
#pragma unroll
    for (int i = 0; i < 32; i += 8) {
        int d = d0 + ty + i, s = s0 + tx;
        __nv_bfloat16 hi, lo;
        split2(t[tx][ty + i], hi, lo);
        size_t base = (size_t)d * K3S + (size_t)(s >> 6) * 192 + (s & 63);
        Vt3[base] = hi; Vt3[base + 64] = hi; Vt3[base + 128] = lo;
    }
}

// ---------------- FFMA-only exp + fused softmax -> tripled P3 ---------------
__device__ __forceinline__ float fexp(float x) {
    float y = fmaxf(x * 1.4426950408889634f, -126.0f);
    float fl = floorf(y);
    float f = y - fl;
    float p = 1.5403530e-4f;
    p = fmaf(p, f, 1.3333558e-3f);
    p = fmaf(p, f, 9.6181291e-3f);
    p = fmaf(p, f, 5.5504109e-2f);
    p = fmaf(p, f, 2.4022651e-1f);
    p = fmaf(p, f, 6.9314718e-1f);
    p = fmaf(p, f, 1.0f);
    int e = (int)fl;
    return __int_as_float((e + 127) << 23) * p;
}

__global__ __launch_bounds__(128) void softmax_p3(const float* __restrict__ Sb,
                                                  __nv_bfloat16* __restrict__ P3) {
    int q = blockIdx.x, h = blockIdx.y;
    int n = (q >> 7) + 1;
    const float* row = Sb + ((size_t)h * S_LEN + q) * S_LEN;
    __nv_bfloat16* prow = P3 + ((size_t)h * S_LEN + q) * K3S;
    int tid = threadIdx.x;
    float v[16];
    float m = -CUDART_INF_F;
    for (int c = 0; c < n; c++) { v[c] = row[(c << 7) + tid]; m = fmaxf(m, v[c]); }
#pragma unroll
    for (int o = 16; o; o >>= 1) m = fmaxf(m, __shfl_xor_sync(~0u, m, o));
    __shared__ float red[4];
    if ((tid & 31) == 0) red[tid >> 5] = m;
    __syncthreads();
    m = fmaxf(fmaxf(red[0], red[1]), fmaxf(red[2], red[3]));
    __syncthreads();
    float s = 0.f;
    for (int c = 0; c < n; c++) { v[c] = fexp(v[c] - m); s += v[c]; }
#pragma unroll
    for (int o = 16; o; o >>= 1) s += __shfl_xor_sync(~0u, s, o);
    if ((tid & 31) == 0) red[tid >> 5] = s;
    __syncthreads();
    s = red[0] + red[1] + red[2] + red[3];
    float inv = __fdividef(1.0f, s);
    for (int c = 0; c < n; c++) {
        float p = v[c] * inv;
        int si = (c << 7) + tid;
        __nv_bfloat16 hi, lo;
        split2(p, hi, lo);
        size_t base = (size_t)(si >> 6) * 192 + (si & 63);
        prow[base] = hi; prow[base + 64] = lo; prow[base + 128] = hi;  // A-pattern
    }
}

// ---------------- launch ----------------------------------------------------
extern "C" void kernel_launch(void* const* d_in, const int* in_sizes, int n_in,
                              void* d_out, int out_size) {
    const float* x  = (const float*)d_in[0];
    const float* wq = (const float*)d_in[1];
    const float* wk = (const float*)d_in[2];
    const float* wv = (const float*)d_in[3];
    const float* wo = (const float*)d_in[4];
    const float* fc = (const float*)d_in[5];
    const float* fs = (const float*)d_in[6];
    float* out = (float*)d_out;

    float *Q, *K, *V, *S;
    __nv_bfloat16 *x3, *wq3, *wk3, *wv3, *wo3, *q3, *k3, *vt3, *p3, *at3;
    cudaGetSymbolAddress((void**)&Q,   g_q);
    cudaGetSymbolAddress((void**)&K,   g_k);
    cudaGetSymbolAddress((void**)&V,   g_v);
    cudaGetSymbolAddress((void**)&S,   g_s);
    cudaGetSymbolAddress((void**)&x3,  g_x3);
    cudaGetSymbolAddress((void**)&wq3, g_wq3);
    cudaGetSymbolAddress((void**)&wk3, g_wk3);
    cudaGetSymbolAddress((void**)&wv3, g_wv3);
    cudaGetSymbolAddress((void**)&wo3, g_wo3);
    cudaGetSymbolAddress((void**)&q3,  g_q3);
    cudaGetSymbolAddress((void**)&k3,  g_k3);
    cudaGetSymbolAddress((void**)&vt3, g_vt3);
    cudaGetSymbolAddress((void**)&p3,  g_p3);
    cudaGetSymbolAddress((void**)&at3, g_at3);

    // operand splitting (bf16 hi/lo, K-tripled); pair-vectorized
    conv_a3<<<(S_LEN * DIM / 2 + 255) / 256, 256>>>(x,  x3,  S_LEN * DIM / 2);
    conv_b3<<<(DIM * DIM / 2 + 255) / 256, 256>>>(wq, wq3, DIM * DIM / 2);
    conv_b3<<<(KV_DIM * DIM / 2 + 255) / 256, 256>>>(wk, wk3, KV_DIM * DIM / 2);
    conv_b3<<<(KV_DIM * DIM / 2 + 255) / 256, 256>>>(wv, wv3, KV_DIM * DIM / 2);
    conv_b3<<<(DIM * DIM / 2 + 255) / 256, 256>>>(wo, wo3, DIM * DIM / 2);

    // QKV projections (tensor cores via mma.sync + ldmatrix)
    gemm3_f32<<<dim3(16, 32), 256>>>(x3, K3DIM, wq3, K3DIM, Q, DIM,    K3DIM / BK);
    gemm3_f32<<<dim3(16,  8), 256>>>(x3, K3DIM, wk3, K3DIM, K, KV_DIM, K3DIM / BK);
    gemm3_f32<<<dim3(16,  8), 256>>>(x3, K3DIM, wv3, K3DIM, V, KV_DIM, K3DIM / BK);

    // RoPE + split (fused)
    rope_conv_q<<<(S_LEN * NH  * 64) / 256, 256>>>(Q, fc, fs, q3);
    rope_conv_k<<<(S_LEN * NKV * 64) / 256, 256>>>(K, fc, fs, k3);
    conv_vt<<<dim3(S_LEN / 32, KV_DIM / 32), dim3(32, 8)>>>(V, vt3);

    // attention: compact triangular score grid -> softmax -> PV (longest first)
    score3<<<dim3(136, NH), 256>>>(q3, k3, S);
    softmax_p3<<<dim3(S_LEN, NH), 128>>>(S, p3);
    pv3<<<dim3(16, NH), 256>>>(p3, vt3, at3);

    // output projection
    gemm3_f32<<<dim3(16, 32), 256>>>(at3, K3DIM, wo3, K3DIM, out, DIM, K3DIM / BK);
}

// round 11
// speedup vs baseline: 2.3218x; 1.1443x over previous
#include <cuda_runtime.h>
#include <cuda_bf16.h>
#include <cuda_fp16.h>
#include <math_constants.h>
#include <cstdint>

#define S_LEN  2048
#define DIM    4096
#define KV_DIM 1024
#define NH     32
#define NKV    8
#define HD     128
#define K3DIM  12288      // 3*4096 (tripled K for projections, bf16 3-split)
#define K3HD   384        // 3*128  (tripled K for scores)
#define K3S    6144       // 3*2048 (tripled K for PV)
#define K2DIM  8192       // 2*4096 (doubled K for WO, fp16 2-split)
#define BK     32
#define SMS    40         // smem row stride in bf16 (32 + 8 pad; 80B)

// ---------------- scratch (module-load allocated) ---------------------------
__device__ __align__(16) float g_q[S_LEN * DIM];
__device__ __align__(16) float g_k[S_LEN * KV_DIM];
__device__ __align__(16) float g_v[S_LEN * KV_DIM];
__device__ __align__(16) __nv_bfloat16 g_x3 [S_LEN * K3DIM];
__device__ __align__(16) __nv_bfloat16 g_wq3[DIM * K3DIM];
__device__ __align__(16) __nv_bfloat16 g_wk3[KV_DIM * K3DIM];
__device__ __align__(16) __nv_bfloat16 g_wv3[KV_DIM * K3DIM];
__device__ __align__(16) __nv_bfloat16 g_q3 [S_LEN * K3DIM];             // roped, A-pat
__device__ __align__(16) __nv_bfloat16 g_k3 [S_LEN * (NKV * K3HD)];      // roped, B-pat
__device__ __align__(16) __nv_bfloat16 g_vt3[KV_DIM * K3S];              // V^T, B-pat
__device__ __align__(16) __half        g_at2[S_LEN * K2DIM];             // attn out, fp16 [hi,lo]
__device__ __align__(16) __half        g_wo2[DIM * K2DIM];               // wo, fp16 [hi,hi]

// ---------------- helpers ----------------------------------------------------
__device__ __forceinline__ void split2(float a, __nv_bfloat16& hi, __nv_bfloat16& lo) {
    hi = __float2bfloat16(a);
    lo = __float2bfloat16(a - __bfloat162float(hi));
}
__device__ __forceinline__ uint32_t s2u(const void* p) {
    uint32_t a;
    asm("{ .reg .u64 t; cvta.to.shared.u64 t, %1; cvt.u32.u64 %0, t; }" : "=r"(a) : "l"(p));
    return a;
}
__device__ __forceinline__ void cpa16(uint32_t s, const void* g) {
    asm volatile("cp.async.cg.shared.global [%0], [%1], 16;" :: "r"(s), "l"(g));
}
__device__ __forceinline__ void cpa_commit() {
    asm volatile("cp.async.commit_group;" ::: "memory");
}
__device__ __forceinline__ void mma_bf16(float* c, const uint32_t* a, const uint32_t* b) {
    asm volatile(
        "mma.sync.aligned.m16n8k16.row.col.f32.bf16.bf16.f32 "
        "{%0,%1,%2,%3}, {%4,%5,%6,%7}, {%8,%9}, {%0,%1,%2,%3};"
        : "+f"(c[0]), "+f"(c[1]), "+f"(c[2]), "+f"(c[3])
        : "r"(a[0]), "r"(a[1]), "r"(a[2]), "r"(a[3]), "r"(b[0]), "r"(b[1]));
}
__device__ __forceinline__ void mma_f16(float* c, const uint32_t* a, const uint32_t* b) {
    asm volatile(
        "mma.sync.aligned.m16n8k16.row.col.f32.f16.f16.f32 "
        "{%0,%1,%2,%3}, {%4,%5,%6,%7}, {%8,%9}, {%0,%1,%2,%3};"
        : "+f"(c[0]), "+f"(c[1]), "+f"(c[2]), "+f"(c[3])
        : "r"(a[0]), "r"(a[1]), "r"(a[2]), "r"(a[3]), "r"(b[0]), "r"(b[1]));
}
__device__ __forceinline__ void ldsm4(uint32_t& r0, uint32_t& r1, uint32_t& r2, uint32_t& r3,
                                      uint32_t addr) {
    asm volatile("ldmatrix.sync.aligned.m8n8.x4.shared.b16 {%0,%1,%2,%3}, [%4];"
                 : "=r"(r0), "=r"(r1), "=r"(r2), "=r"(r3) : "r"(addr));
}

// ---------------- shared GEMM core (proven) ---------------------------------
struct GemmSmem {
    __align__(16) __nv_bfloat16 A[2][128 * SMS];
    __align__(16) __nv_bfloat16 B[2][128 * SMS];
};

__device__ __forceinline__ void issue_tile(uint32_t sa, uint32_t sb,
                                           const __nv_bfloat16* __restrict__ A3, int lda3,
                                           const __nv_bfloat16* __restrict__ B3, int ldb3,
                                           int k0, int tid) {
#pragma unroll
    for (int i = 0; i < 2; i++) {
        int idx = i * 256 + tid;
        int r = idx >> 2, c = idx & 3;
        cpa16(sa + (r * SMS + c * 8) * 2, A3 + (size_t)r * lda3 + k0 + c * 8);
    }
#pragma unroll
    for (int i = 0; i < 2; i++) {
        int idx = i * 256 + tid;
        int r = idx >> 2, c = idx & 3;
        cpa16(sb + (r * SMS + c * 8) * 2, B3 + (size_t)r * ldb3 + k0 + c * 8);
    }
    cpa_commit();
}
__device__ __forceinline__ void issue_tile_b(uint32_t sb,
                                             const __nv_bfloat16* __restrict__ B3, int ldb3,
                                             int k0, int tid) {
#pragma unroll
    for (int i = 0; i < 2; i++) {
        int idx = i * 256 + tid;
        int r = idx >> 2, c = idx & 3;
        cpa16(sb + (r * SMS + c * 8) * 2, B3 + (size_t)r * ldb3 + k0 + c * 8);
    }
    cpa_commit();
}

template <bool F16>
__device__ __forceinline__ void gemm_main(const __nv_bfloat16* __restrict__ A3, int lda3,
                                          const __nv_bfloat16* __restrict__ B3, int ldb3,
                                          int nchunks, GemmSmem* sm, float (&acc)[4][4][4]) {
    int tid = threadIdx.x, wid = tid >> 5, lane = tid & 31;
    int wm = (wid & 1) * 64, wn = (wid >> 1) * 32;
    uint32_t sa0 = s2u(sm->A[0]), sb0 = s2u(sm->B[0]);
    uint32_t sa1 = s2u(sm->A[1]), sb1 = s2u(sm->B[1]);

    int a_row = wm + (lane & 15);
    int a_kh  = (lane >> 4) * 8;
    int b_row = wn + (lane & 7) + ((lane >> 4) ? 8 : 0);
    int b_kh  = ((lane >> 3) & 1) * 8;
    uint32_t a_off = (uint32_t)(a_row * SMS + a_kh) * 2;
    uint32_t b_off = (uint32_t)(b_row * SMS + b_kh) * 2;

    issue_tile(sa0, sb0, A3, lda3, B3, ldb3, 0, tid);

    for (int c = 0; c < nchunks; c++) {
        int b = c & 1;
        if (c + 1 < nchunks) {
            issue_tile(b ? sa0 : sa1, b ? sb0 : sb1, A3, lda3, B3, ldb3, (c + 1) * BK, tid);
            asm volatile("cp.async.wait_group 1;" ::: "memory");
        } else {
            asm volatile("cp.async.wait_group 0;" ::: "memory");
        }
        __syncthreads();
        uint32_t As_u = (b ? sa1 : sa0);
        uint32_t Bs_u = (b ? sb1 : sb0);
#pragma unroll
        for (int ks = 0; ks < BK; ks += 16) {
            uint32_t af[4][4], bf[4][2];
            uint32_t aa = As_u + a_off + ks * 2;
            uint32_t ba = Bs_u + b_off + ks * 2;
#pragma unroll
            for (int mi = 0; mi < 4; mi++)
                ldsm4(af[mi][0], af[mi][1], af[mi][2], af[mi][3], aa + mi * 16 * SMS * 2);
#pragma unroll
            for (int njp = 0; njp < 2; njp++)
                ldsm4(bf[2 * njp][0], bf[2 * njp][1], bf[2 * njp + 1][0], bf[2 * njp + 1][1],
                      ba + njp * 16 * SMS * 2);
#pragma unroll
            for (int mi = 0; mi < 4; mi++)
#pragma unroll
                for (int nj = 0; nj < 4; nj++) {
                    if (F16) mma_f16(acc[mi][nj], af[mi], bf[nj]);
                    else     mma_bf16(acc[mi][nj], af[mi], bf[nj]);
                }
        }
        __syncthreads();
    }
}

// ---------------- GEMM -> fp32 C  (QKV bf16-3split, WO fp16-2split) ---------
template <bool F16>
__global__ __launch_bounds__(256) void gemm_f32_k(const __nv_bfloat16* __restrict__ A3, int lda3,
                                                  const __nv_bfloat16* __restrict__ B3, int ldb3,
                                                  float* __restrict__ C, int ldc, int nchunks) {
    __shared__ GemmSmem sm;
    float acc[4][4][4] = {};
    gemm_main<F16>(A3 + (size_t)blockIdx.x * 128 * lda3, lda3,
                   B3 + (size_t)blockIdx.y * 128 * ldb3, ldb3, nchunks, &sm, acc);
    int tid = threadIdx.x, wid = tid >> 5, lane = tid & 31;
    int wm = (wid & 1) * 64, wn = (wid >> 1) * 32;
    int g = lane >> 2, t = lane & 3;
#pragma unroll
    for (int mi = 0; mi < 4; mi++)
#pragma unroll
        for (int nj = 0; nj < 4; nj++) {
            int r0 = blockIdx.x * 128 + wm + mi * 16 + g;
            int c0 = blockIdx.y * 128 + wn + nj * 8 + t * 2;
            *(float2*)(C + (size_t)r0 * ldc + c0)       = make_float2(acc[mi][nj][0], acc[mi][nj][1]);
            *(float2*)(C + (size_t)(r0 + 8) * ldc + c0) = make_float2(acc[mi][nj][2], acc[mi][nj][3]);
        }
}

// ---------------- FFMA-only exp ---------------------------------------------
__device__ __forceinline__ float fexp(float x) {
    float y = fmaxf(x * 1.4426950408889634f, -126.0f);
    float fl = floorf(y);
    float f = y - fl;
    float p = 1.5403530e-4f;
    p = fmaf(p, f, 1.3333558e-3f);
    p = fmaf(p, f, 9.6181291e-3f);
    p = fmaf(p, f, 5.5504109e-2f);
    p = fmaf(p, f, 2.4022651e-1f);
    p = fmaf(p, f, 6.9314718e-1f);
    p = fmaf(p, f, 1.0f);
    int e = (int)fl;
    return __int_as_float((e + 127) << 23) * p;
}

// ---------------- fused flash attention -------------------------------------
// Block: q-tile (128 rows) x head. Warp w owns q rows [16w,16w+16).
// Per kv tile: S = QK^T (stream Q/K), online softmax in regs,
// P->bf16 hi/lo frags in regs (C-layout == A-layout), O += P@V^T (stream V).
__global__ __launch_bounds__(256) void attn_fused(const __nv_bfloat16* __restrict__ Q3,
                                                  const __nv_bfloat16* __restrict__ K3,
                                                  const __nv_bfloat16* __restrict__ Vt3,
                                                  __half* __restrict__ AT2) {
    int bx = 15 - (int)blockIdx.x;             // longest first
    int h = blockIdx.y, kg = h >> 2;
    __shared__ GemmSmem sm;
    int tid = threadIdx.x, wid = tid >> 5, lane = tid & 31;
    int g = lane >> 2, t = lane & 3;

    uint32_t sa0 = s2u(sm.A[0]), sb0 = s2u(sm.B[0]);
    uint32_t sa1 = s2u(sm.A[1]), sb1 = s2u(sm.B[1]);

    int a_row = wid * 16 + (lane & 15);
    int a_kh  = (lane >> 4) * 8;
    uint32_t a_off = (uint32_t)(a_row * SMS + a_kh) * 2;
    int b_row = (lane & 7) + ((lane >> 4) ? 8 : 0);
    int b_kh  = ((lane >> 3) & 1) * 8;
    uint32_t b_off = (uint32_t)(b_row * SMS + b_kh) * 2;

    const __nv_bfloat16* Qb = Q3 + (size_t)bx * 128 * K3DIM + h * K3HD;
    const int ldK = NKV * K3HD;
    const __nv_bfloat16* Kb = K3 + (size_t)kg * K3HD;
    const __nv_bfloat16* Vb = Vt3 + (size_t)kg * 128 * K3S;

    float m0 = -CUDART_INF_F, m1 = -CUDART_INF_F, l0 = 0.f, l1 = 0.f;
    float o[16][4];
#pragma unroll
    for (int dj = 0; dj < 16; dj++) { o[dj][0] = o[dj][1] = o[dj][2] = o[dj][3] = 0.f; }

    const float scale = 0.088388347648318447f;   // 1/sqrt(128)
    int row0 = bx * 128 + wid * 16 + g;
    int row1 = row0 + 8;

    for (int by = 0; by <= bx; by++) {
        // ---------- S = Q K^T ----------
        float acc[16][4] = {};
        const __nv_bfloat16* Kt = Kb + (size_t)by * 128 * ldK;
        issue_tile(sa0, sb0, Qb, K3DIM, Kt, ldK, 0, tid);
        for (int c = 0; c < 12; c++) {
            int b = c & 1;
            if (c + 1 < 12) {
                issue_tile(b ? sa0 : sa1, b ? sb0 : sb1, Qb, K3DIM, Kt, ldK, (c + 1) * BK, tid);
                asm volatile("cp.async.wait_group 1;" ::: "memory");
            } else {
                asm volatile("cp.async.wait_group 0;" ::: "memory");
            }
            __syncthreads();
            uint32_t Au = b ? sa1 : sa0, Bu = b ? sb1 : sb0;
#pragma unroll
            for (int ks = 0; ks < BK; ks += 16) {
                uint32_t af[4], bf[16][2];
                ldsm4(af[0], af[1], af[2], af[3], Au + a_off + ks * 2);
#pragma unroll
                for (int njp = 0; njp < 8; njp++)
                    ldsm4(bf[2 * njp][0], bf[2 * njp][1], bf[2 * njp + 1][0], bf[2 * njp + 1][1],
                          Bu + b_off + ks * 2 + njp * 16 * SMS * 2);
#pragma unroll
                for (int nj = 0; nj < 16; nj++)
                    mma_bf16(acc[nj], af, bf[nj]);
            }
            __syncthreads();
        }
        // ---------- online softmax ----------
        bool diag = (by == bx);
        float rx0 = -CUDART_INF_F, rx1 = -CUDART_INF_F;
#pragma unroll
        for (int nj = 0; nj < 16; nj++) {
            int col = by * 128 + nj * 8 + 2 * t;
            float v0 = acc[nj][0] * scale, v1 = acc[nj][1] * scale;
            float v2 = acc[nj][2] * scale, v3 = acc[nj][3] * scale;
            if (diag) {
                if (col     > row0) v0 = -CUDART_INF_F;
                if (col + 1 > row0) v1 = -CUDART_INF_F;
                if (col     > row1) v2 = -CUDART_INF_F;
                if (col + 1 > row1) v3 = -CUDART_INF_F;
            }
            acc[nj][0] = v0; acc[nj][1] = v1; acc[nj][2] = v2; acc[nj][3] = v3;
            rx0 = fmaxf(rx0, fmaxf(v0, v1)); rx1 = fmaxf(rx1, fmaxf(v2, v3));
        }
        rx0 = fmaxf(rx0, __shfl_xor_sync(~0u, rx0, 1));
        rx0 = fmaxf(rx0, __shfl_xor_sync(~0u, rx0, 2));
        rx1 = fmaxf(rx1, __shfl_xor_sync(~0u, rx1, 1));
        rx1 = fmaxf(rx1, __shfl_xor_sync(~0u, rx1, 2));
        float mn0 = fmaxf(m0, rx0), mn1 = fmaxf(m1, rx1);
        float al0 = fexp(m0 - mn0), al1 = fexp(m1 - mn1);
        m0 = mn0; m1 = mn1;
        float rs0 = 0.f, rs1 = 0.f;
        uint32_t ph[16][2], pl[16][2];
#pragma unroll
        for (int nj = 0; nj < 16; nj++) {
            float p0 = fexp(acc[nj][0] - mn0), p1 = fexp(acc[nj][1] - mn0);
            float p2 = fexp(acc[nj][2] - mn1), p3 = fexp(acc[nj][3] - mn1);
            rs0 += p0 + p1; rs1 += p2 + p3;
            __nv_bfloat16 h0, q0, h1, q1, h2, q2, h3, q3;
            split2(p0, h0, q0); split2(p1, h1, q1);
            split2(p2, h2, q2); split2(p3, h3, q3);
            __nv_bfloat162 a01; a01.x = h0; a01.y = h1;
            __nv_bfloat162 a23; a23.x = h2; a23.y = h3;
            __nv_bfloat162 b01; b01.x = q0; b01.y = q1;
            __nv_bfloat162 b23; b23.x = q2; b23.y = q3;
            ph[nj][0] = *(uint32_t*)&a01; ph[nj][1] = *(uint32_t*)&a23;
            pl[nj][0] = *(uint32_t*)&b01; pl[nj][1] = *(uint32_t*)&b23;
        }
        rs0 += __shfl_xor_sync(~0u, rs0, 1); rs0 += __shfl_xor_sync(~0u, rs0, 2);
        rs1 += __shfl_xor_sync(~0u, rs1, 1); rs1 += __shfl_xor_sync(~0u, rs1, 2);
        l0 = l0 * al0 + rs0; l1 = l1 * al1 + rs1;
#pragma unroll
        for (int dj = 0; dj < 16; dj++) {
            o[dj][0] *= al0; o[dj][1] *= al0; o[dj][2] *= al1; o[dj][3] *= al1;
        }
        // ---------- O += P @ V^T (tripled kv: A-pat [hi,lo,hi] x B-pat [hi,hi,lo]) ----------
        const __nv_bfloat16* Vt = Vb + (size_t)by * 384;
        issue_tile_b(sb0, Vt, K3S, 0, tid);
#pragma unroll
        for (int c = 0; c < 12; c++) {
            int b = c & 1;
            if (c + 1 < 12) {
                issue_tile_b(b ? sb0 : sb1, Vt, K3S, (c + 1) * BK, tid);
                asm volatile("cp.async.wait_group 1;" ::: "memory");
            } else {
                asm volatile("cp.async.wait_group 0;" ::: "memory");
            }
            __syncthreads();
            uint32_t Bu = b ? sb1 : sb0;
#pragma unroll
            for (int ks = 0; ks < BK; ks += 16) {
                int kk  = c * 2 + (ks >> 4);         // tripled k16 index 0..23
                int b64 = kk >> 2;
                int sel = b64 % 3;                   // 0:hi 1:lo 2:hi
                int j16 = (b64 / 3) * 4 + (kk & 3);  // kv 16-chunk 0..7
                uint32_t af[4];
                if (sel == 1) {
                    af[0] = pl[2 * j16][0]; af[1] = pl[2 * j16][1];
                    af[2] = pl[2 * j16 + 1][0]; af[3] = pl[2 * j16 + 1][1];
                } else {
                    af[0] = ph[2 * j16][0]; af[1] = ph[2 * j16][1];
                    af[2] = ph[2 * j16 + 1][0]; af[3] = ph[2 * j16 + 1][1];
                }
                uint32_t bf[16][2];
#pragma unroll
                for (int njp = 0; njp < 8; njp++)
                    ldsm4(bf[2 * njp][0], bf[2 * njp][1], bf[2 * njp + 1][0], bf[2 * njp + 1][1],
                          Bu + b_off + ks * 2 + njp * 16 * SMS * 2);
#pragma unroll
                for (int dj = 0; dj < 16; dj++)
                    mma_bf16(o[dj], af, bf[dj]);
            }
            __syncthreads();
        }
    }
    // ---------- epilogue: O/l -> fp16 [hi,lo] at2 ----------
    float inv0 = __fdividef(1.f, l0), inv1 = __fdividef(1.f, l1);
#pragma unroll
    for (int dj = 0; dj < 16; dj++) {
        int d = h * 128 + dj * 8 + 2 * t;
        size_t kb = (size_t)(d >> 5) * 64 + (d & 31);
        float v0 = o[dj][0] * inv0, v1 = o[dj][1] * inv0;
        float v2 = o[dj][2] * inv1, v3 = o[dj][3] * inv1;
        __half h0 = __float2half(v0), h1 = __float2half(v1);
        __half h2 = __float2half(v2), h3 = __float2half(v3);
        __half e0 = __float2half(v0 - __half2float(h0));
        __half e1 = __float2half(v1 - __half2float(h1));
        __half e2 = __float2half(v2 - __half2float(h2));
        __half e3 = __float2half(v3 - __half2float(h3));
        __half2 hp0; hp0.x = h0; hp0.y = h1;
        __half2 lp0; lp0.x = e0; lp0.y = e1;
        __half2 hp1; hp1.x = h2; hp1.y = h3;
        __half2 lp1; lp1.x = e2; lp1.y = e3;
        __half* p0 = AT2 + (size_t)row0 * K2DIM + kb;
        __half* p1 = AT2 + (size_t)row1 * K2DIM + kb;
        *(__half2*)(p0) = hp0; *(__half2*)(p0 + 32) = lp0;
        *(__half2*)(p1) = hp1; *(__half2*)(p1 + 32) = lp1;
    }
}

// ---------------- conversion kernels ----------------------------------------
// bf16 A-pat: [hi,lo,hi]  B-pat: [hi,hi,lo]  per 64-elem K block
__global__ void conv_a3(const float* __restrict__ W, __nv_bfloat16* __restrict__ W3, int total2) {
    int idx = blockIdx.x * 256 + threadIdx.x;
    if (idx >= total2) return;
    int k = (idx & 2047) * 2, m = idx >> 11;
    float2 w = *(const float2*)(W + (size_t)m * 4096 + k);
    __nv_bfloat16 h0, l0, h1, l1;
    split2(w.x, h0, l0); split2(w.y, h1, l1);
    __nv_bfloat162 hp; hp.x = h0; hp.y = h1;
    __nv_bfloat162 lp; lp.x = l0; lp.y = l1;
    size_t base = (size_t)m * K3DIM + (size_t)(k >> 6) * 192 + (k & 63);
    *(__nv_bfloat162*)(W3 + base)       = hp;
    *(__nv_bfloat162*)(W3 + base + 64)  = lp;
    *(__nv_bfloat162*)(W3 + base + 128) = hp;
}
__global__ void conv_b3(const float* __restrict__ W, __nv_bfloat16* __restrict__ W3, int total2) {
    int idx = blockIdx.x * 256 + threadIdx.x;
    if (idx >= total2) return;
    int k = (idx & 2047) * 2, m = idx >> 11;
    float2 w = *(const float2*)(W + (size_t)m * 4096 + k);
    __nv_bfloat16 h0, l0, h1, l1;
    split2(w.x, h0, l0); split2(w.y, h1, l1);
    __nv_bfloat162 hp; hp.x = h0; hp.y = h1;
    __nv_bfloat162 lp; lp.x = l0; lp.y = l1;
    size_t base = (size_t)m * K3DIM + (size_t)(k >> 6) * 192 + (k & 63);
    *(__nv_bfloat162*)(W3 + base)       = hp;
    *(__nv_bfloat162*)(W3 + base + 64)  = hp;
    *(__nv_bfloat162*)(W3 + base + 128) = lp;
}
// fp16 B-pat for WO: [hi,hi] per 32-elem K block
__global__ void conv_wo2(const float* __restrict__ W, __half* __restrict__ W2, int total2) {
    int idx = blockIdx.x * 256 + threadIdx.x;
    if (idx >= total2) return;
    int k = (idx & 2047) * 2, m = idx >> 11;
    float2 w = *(const float2*)(W + (size_t)m * 4096 + k);
    __half2 hp; hp.x = __float2half(w.x); hp.y = __float2half(w.y);
    size_t base = (size_t)m * K2DIM + (size_t)(k >> 5) * 64 + (k & 31);
    *(__half2*)(W2 + base)      = hp;
    *(__half2*)(W2 + base + 32) = hp;
}

__global__ void rope_conv_q(const float* __restrict__ Q, const float* __restrict__ fc,
                            const float* __restrict__ fs, __nv_bfloat16* __restrict__ Q3) {
    int idx = blockIdx.x * 256 + threadIdx.x;           // S*NH*64
    int i = idx & 63, h = (idx >> 6) & 31, s = idx >> 11;
    float c = fc[(s << 6) + i], sn = fs[(s << 6) + i];
    const float* qp = Q + (size_t)s * DIM + h * HD + 2 * i;
    float xr = qp[0], xi = qp[1];
    float vr = xr * c - xi * sn, vi = xr * sn + xi * c;
    int d0 = 2 * i;
    size_t base = (size_t)s * K3DIM + h * K3HD + (size_t)(d0 >> 6) * 192 + (d0 & 63);
    __nv_bfloat16 hr, lr, hi_, li;
    split2(vr, hr, lr); split2(vi, hi_, li);
    __nv_bfloat162 hp; hp.x = hr; hp.y = hi_;
    __nv_bfloat162 lp; lp.x = lr; lp.y = li;
    *(__nv_bfloat162*)(Q3 + base)       = hp;  // A-pattern
    *(__nv_bfloat162*)(Q3 + base + 64)  = lp;
    *(__nv_bfloat162*)(Q3 + base + 128) = hp;
}
__global__ void rope_conv_k(const float* __restrict__ K, const float* __restrict__ fc,
                            const float* __restrict__ fs, __nv_bfloat16* __restrict__ K3) {
    int idx = blockIdx.x * 256 + threadIdx.x;           // S*NKV*64
    int i = idx & 63, h = (idx >> 6) & 7, s = idx >> 9;
    float c = fc[(s << 6) + i], sn = fs[(s << 6) + i];
    const float* kp = K + (size_t)s * KV_DIM + h * HD + 2 * i;
    float xr = kp[0], xi = kp[1];
    float vr = xr * c - xi * sn, vi = xr * sn + xi * c;
    int d0 = 2 * i;
    size_t base = (size_t)s * (NKV * K3HD) + h * K3HD + (size_t)(d0 >> 6) * 192 + (d0 & 63);
    __nv_bfloat16 hr, lr, hi_, li;
    split2(vr, hr, lr); split2(vi, hi_, li);
    __nv_bfloat162 hp; hp.x = hr; hp.y = hi_;
    __nv_bfloat162 lp; lp.x = lr; lp.y = li;
    *(__nv_bfloat162*)(K3 + base)       = hp;  // B-pattern
    *(__nv_bfloat162*)(K3 + base + 64)  = hp;
    *(__nv_bfloat162*)(K3 + base + 128) = lp;
}
// V [S][KV_DIM] -> Vt3 [d=1024][3*2048] B-pattern (smem transpose)
__global__ void conv_vt(const float* __restrict__ V, __nv_bfloat16* __restrict__ Vt3) {
    __shared__ float t[32][33];
    int s0 = blockIdx.x * 32, d0 = blockIdx.y * 32;
    int tx = threadIdx.x, ty = threadIdx.y;
#pragma unroll
    for (int i = 0; i < 32; i += 8)
        t[ty + i][tx] = V[(size_t)(s0 + ty + i) * KV_DIM + d0 + tx];
    __syncthreads();
#pragma unroll
    for (int i = 0; i < 32; i += 8) {
        int d = d0 + ty + i, s = s0 + tx;
        __nv_bfloat16 hi, lo;
        split2(t[tx][ty + i], hi, lo);
        size_t base = (size_t)d * K3S + (size_t)(s >> 6) * 192 + (s & 63);
        Vt3[base] = hi; Vt3[base + 64] = hi; Vt3[base + 128] = lo;
    }
}

// ---------------- launch ----------------------------------------------------
extern "C" void kernel_launch(void* const* d_in, const int* in_sizes, int n_in,
                              void* d_out, int out_size) {
    const float* x  = (const float*)d_in[0];
    const float* wq = (const float*)d_in[1];
    const float* wk = (const float*)d_in[2];
    const float* wv = (const float*)d_in[3];
    const float* wo = (const float*)d_in[4];
    const float* fc = (const float*)d_in[5];
    const float* fs = (const float*)d_in[6];
    float* out = (float*)d_out;

    float *Q, *K, *V;
    __nv_bfloat16 *x3, *wq3, *wk3, *wv3, *q3, *k3, *vt3;
    __half *at2, *wo2;
    cudaGetSymbolAddress((void**)&Q,   g_q);
    cudaGetSymbolAddress((void**)&K,   g_k);
    cudaGetSymbolAddress((void**)&V,   g_v);
    cudaGetSymbolAddress((void**)&x3,  g_x3);
    cudaGetSymbolAddress((void**)&wq3, g_wq3);
    cudaGetSymbolAddress((void**)&wk3, g_wk3);
    cudaGetSymbolAddress((void**)&wv3, g_wv3);
    cudaGetSymbolAddress((void**)&q3,  g_q3);
    cudaGetSymbolAddress((void**)&k3,  g_k3);
    cudaGetSymbolAddress((void**)&vt3, g_vt3);
    cudaGetSymbolAddress((void**)&at2, g_at2);
    cudaGetSymbolAddress((void**)&wo2, g_wo2);

    // operand splitting
    conv_a3<<<(S_LEN * DIM / 2 + 255) / 256, 256>>>(x,  x3,  S_LEN * DIM / 2);
    conv_b3<<<(DIM * DIM / 2 + 255) / 256, 256>>>(wq, wq3, DIM * DIM / 2);
    conv_b3<<<(KV_DIM * DIM / 2 + 255) / 256, 256>>>(wk, wk3, KV_DIM * DIM / 2);
    conv_b3<<<(KV_DIM * DIM / 2 + 255) / 256, 256>>>(wv, wv3, KV_DIM * DIM / 2);
    conv_wo2<<<(DIM * DIM / 2 + 255) / 256, 256>>>(wo, wo2, DIM * DIM / 2);

    // QKV projections (bf16 3-split)
    gemm_f32_k<false><<<dim3(16, 32), 256>>>(x3, K3DIM, wq3, K3DIM, Q, DIM,    K3DIM / BK);
    gemm_f32_k<false><<<dim3(16,  8), 256>>>(x3, K3DIM, wk3, K3DIM, K, KV_DIM, K3DIM / BK);
    gemm_f32_k<false><<<dim3(16,  8), 256>>>(x3, K3DIM, wv3, K3DIM, V, KV_DIM, K3DIM / BK);

    // RoPE + split (fused)
    rope_conv_q<<<(S_LEN * NH  * 64) / 256, 256>>>(Q, fc, fs, q3);
    rope_conv_k<<<(S_LEN * NKV * 64) / 256, 256>>>(K, fc, fs, k3);
    conv_vt<<<dim3(S_LEN / 32, KV_DIM / 32), dim3(32, 8)>>>(V, vt3);

    // fused attention (score + softmax + PV), writes fp16 [hi,lo] at2
    attn_fused<<<dim3(16, NH), 256>>>(q3, k3, vt3, at2);

    // output projection (fp16 2-split)
    gemm_f32_k<true><<<dim3(16, 32), 256>>>(
        (const __nv_bfloat16*)at2, K2DIM, (const __nv_bfloat16*)wo2, K2DIM, out, DIM, K2DIM / BK);
}

// round 13
// speedup vs baseline: 2.4333x; 1.0480x over previous
#include <cuda_runtime.h>
#include <cuda_bf16.h>
#include <cuda_fp16.h>
#include <math_constants.h>
#include <cstdint>

#define S_LEN  2048
#define DIM    4096
#define KV_DIM 1024
#define NH     32
#define NKV    8
#define HD     128
#define K3DIM  12288      // 3*4096 (tripled K for projections, bf16 3-split)
#define K3HD   384        // 3*128  (tripled K for scores)
#define K3S    6144       // 3*2048 (tripled K for PV)
#define K2DIM  8192       // 2*4096 (doubled K for WO, fp16 2-split)
#define BK     32
#define SMS    40         // smem row stride in bf16 (32 + 8 pad; 80B)

// ---------------- scratch (module-load allocated) ---------------------------
__device__ __align__(16) float g_q[S_LEN * DIM];
__device__ __align__(16) float g_k[S_LEN * KV_DIM];
__device__ __align__(16) float g_v[S_LEN * KV_DIM];
__device__ __align__(16) __nv_bfloat16 g_x3 [S_LEN * K3DIM];
__device__ __align__(16) __nv_bfloat16 g_wq3[DIM * K3DIM];
__device__ __align__(16) __nv_bfloat16 g_wk3[KV_DIM * K3DIM];
__device__ __align__(16) __nv_bfloat16 g_wv3[KV_DIM * K3DIM];
__device__ __align__(16) __nv_bfloat16 g_q3 [S_LEN * K3DIM];             // roped, A-pat
__device__ __align__(16) __nv_bfloat16 g_k3 [S_LEN * (NKV * K3HD)];      // roped, B-pat
__device__ __align__(16) __nv_bfloat16 g_vt3[KV_DIM * K3S];              // V^T, B-pat
__device__ __align__(16) __half        g_at2[S_LEN * K2DIM];             // attn out, fp16 [hi,lo]
__device__ __align__(16) __half        g_wo2[DIM * K2DIM];               // wo, fp16 [hi,hi]

// ---------------- helpers ----------------------------------------------------
__device__ __forceinline__ void split2(float a, __nv_bfloat16& hi, __nv_bfloat16& lo) {
    hi = __float2bfloat16(a);
    lo = __float2bfloat16(a - __bfloat162float(hi));
}
__device__ __forceinline__ uint32_t s2u(const void* p) {
    uint32_t a;
    asm("{ .reg .u64 t; cvta.to.shared.u64 t, %1; cvt.u32.u64 %0, t; }" : "=r"(a) : "l"(p));
    return a;
}
__device__ __forceinline__ void cpa16(uint32_t s, const void* g) {
    asm volatile("cp.async.cg.shared.global [%0], [%1], 16;" :: "r"(s), "l"(g));
}
__device__ __forceinline__ void cpa_commit() {
    asm volatile("cp.async.commit_group;" ::: "memory");
}
__device__ __forceinline__ void cpa_wait(int more) {   // wait until <= more pending
    if (more) asm volatile("cp.async.wait_group 1;" ::: "memory");
    else      asm volatile("cp.async.wait_group 0;" ::: "memory");
}
__device__ __forceinline__ void mma_bf16(float* c, const uint32_t* a, const uint32_t* b) {
    asm volatile(
        "mma.sync.aligned.m16n8k16.row.col.f32.bf16.bf16.f32 "
        "{%0,%1,%2,%3}, {%4,%5,%6,%7}, {%8,%9}, {%0,%1,%2,%3};"
        : "+f"(c[0]), "+f"(c[1]), "+f"(c[2]), "+f"(c[3])
        : "r"(a[0]), "r"(a[1]), "r"(a[2]), "r"(a[3]), "r"(b[0]), "r"(b[1]));
}
__device__ __forceinline__ void mma_f16(float* c, const uint32_t* a, const uint32_t* b) {
    asm volatile(
        "mma.sync.aligned.m16n8k16.row.col.f32.f16.f16.f32 "
        "{%0,%1,%2,%3}, {%4,%5,%6,%7}, {%8,%9}, {%0,%1,%2,%3};"
        : "+f"(c[0]), "+f"(c[1]), "+f"(c[2]), "+f"(c[3])
        : "r"(a[0]), "r"(a[1]), "r"(a[2]), "r"(a[3]), "r"(b[0]), "r"(b[1]));
}
__device__ __forceinline__ void ldsm4(uint32_t& r0, uint32_t& r1, uint32_t& r2, uint32_t& r3,
                                      uint32_t addr) {
    asm volatile("ldmatrix.sync.aligned.m8n8.x4.shared.b16 {%0,%1,%2,%3}, [%4];"
                 : "=r"(r0), "=r"(r1), "=r"(r2), "=r"(r3) : "r"(addr));
}

// ---------------- 3-stage pipelined GEMM core -------------------------------
struct Stage {
    __align__(16) __nv_bfloat16 A[128 * SMS];
    __align__(16) __nv_bfloat16 B[128 * SMS];
};
#define SMEM_BYTES (3 * (int)sizeof(Stage))

__device__ __forceinline__ void issue_tile(uint32_t sa, uint32_t sb,
                                           const __nv_bfloat16* __restrict__ A3, int lda3,
                                           const __nv_bfloat16* __restrict__ B3, int ldb3,
                                           int k0, int tid) {
#pragma unroll
    for (int i = 0; i < 2; i++) {
        int idx = i * 256 + tid;
        int r = idx >> 2, c = idx & 3;
        cpa16(sa + (r * SMS + c * 8) * 2, A3 + (size_t)r * lda3 + k0 + c * 8);
    }
#pragma unroll
    for (int i = 0; i < 2; i++) {
        int idx = i * 256 + tid;
        int r = idx >> 2, c = idx & 3;
        cpa16(sb + (r * SMS + c * 8) * 2, B3 + (size_t)r * ldb3 + k0 + c * 8);
    }
    cpa_commit();
}
__device__ __forceinline__ void issue_tile_b(uint32_t sb,
                                             const __nv_bfloat16* __restrict__ B3, int ldb3,
                                             int k0, int tid) {
#pragma unroll
    for (int i = 0; i < 2; i++) {
        int idx = i * 256 + tid;
        int r = idx >> 2, c = idx & 3;
        cpa16(sb + (r * SMS + c * 8) * 2, B3 + (size_t)r * ldb3 + k0 + c * 8);
    }
    cpa_commit();
}

// Block 128x128 C, 256 threads; warp w: 64x32 tile. One __syncthreads per chunk.
template <bool F16>
__device__ __forceinline__ void gemm_main(const __nv_bfloat16* __restrict__ A3, int lda3,
                                          const __nv_bfloat16* __restrict__ B3, int ldb3,
                                          int nchunks, Stage* st, float (&acc)[4][4][4]) {
    int tid = threadIdx.x, wid = tid >> 5, lane = tid & 31;
    int wm = (wid & 1) * 64, wn = (wid >> 1) * 32;
    uint32_t sa[3], sb[3];
#pragma unroll
    for (int s = 0; s < 3; s++) { sa[s] = s2u(st[s].A); sb[s] = s2u(st[s].B); }

    int a_row = wm + (lane & 15);
    int a_kh  = (lane >> 4) * 8;
    int b_row = wn + (lane & 7) + ((lane >> 4) ? 8 : 0);
    int b_kh  = ((lane >> 3) & 1) * 8;
    uint32_t a_off = (uint32_t)(a_row * SMS + a_kh) * 2;
    uint32_t b_off = (uint32_t)(b_row * SMS + b_kh) * 2;

    issue_tile(sa[0], sb[0], A3, lda3, B3, ldb3, 0, tid);
    if (nchunks > 1) issue_tile(sa[1], sb[1], A3, lda3, B3, ldb3, BK, tid);

    for (int c = 0; c < nchunks; c++) {
        cpa_wait(c + 1 < nchunks);
        __syncthreads();
        if (c + 2 < nchunks)
            issue_tile(sa[(c + 2) % 3], sb[(c + 2) % 3], A3, lda3, B3, ldb3, (c + 2) * BK, tid);
        uint32_t Au = sa[c % 3], Bu = sb[c % 3];
#pragma unroll
        for (int ks = 0; ks < BK; ks += 16) {
            uint32_t af[4][4], bf[4][2];
            uint32_t aa = Au + a_off + ks * 2;
            uint32_t ba = Bu + b_off + ks * 2;
#pragma unroll
            for (int mi = 0; mi < 4; mi++)
                ldsm4(af[mi][0], af[mi][1], af[mi][2], af[mi][3], aa + mi * 16 * SMS * 2);
#pragma unroll
            for (int njp = 0; njp < 2; njp++)
                ldsm4(bf[2 * njp][0], bf[2 * njp][1], bf[2 * njp + 1][0], bf[2 * njp + 1][1],
                      ba + njp * 16 * SMS * 2);
#pragma unroll
            for (int mi = 0; mi < 4; mi++)
#pragma unroll
                for (int nj = 0; nj < 4; nj++) {
                    if (F16) mma_f16(acc[mi][nj], af[mi], bf[nj]);
                    else     mma_bf16(acc[mi][nj], af[mi], bf[nj]);
                }
        }
    }
    __syncthreads();
}

// ---------------- GEMM -> fp32 C  (QKV bf16-3split, WO fp16-2split) ---------
template <bool F16>
__global__ __launch_bounds__(256) void gemm_f32_k(const __nv_bfloat16* __restrict__ A3, int lda3,
                                                  const __nv_bfloat16* __restrict__ B3, int ldb3,
                                                  float* __restrict__ C, int ldc, int nchunks) {
    extern __shared__ char smraw[];
    Stage* st = (Stage*)smraw;
    float acc[4][4][4] = {};
    gemm_main<F16>(A3 + (size_t)blockIdx.x * 128 * lda3, lda3,
                   B3 + (size_t)blockIdx.y * 128 * ldb3, ldb3, nchunks, st, acc);
    int tid = threadIdx.x, wid = tid >> 5, lane = tid & 31;
    int wm = (wid & 1) * 64, wn = (wid >> 1) * 32;
    int g = lane >> 2, t = lane & 3;
#pragma unroll
    for (int mi = 0; mi < 4; mi++)
#pragma unroll
        for (int nj = 0; nj < 4; nj++) {
            int r0 = blockIdx.x * 128 + wm + mi * 16 + g;
            int c0 = blockIdx.y * 128 + wn + nj * 8 + t * 2;
            *(float2*)(C + (size_t)r0 * ldc + c0)       = make_float2(acc[mi][nj][0], acc[mi][nj][1]);
            *(float2*)(C + (size_t)(r0 + 8) * ldc + c0) = make_float2(acc[mi][nj][2], acc[mi][nj][3]);
        }
}

// ---------------- FFMA-only exp ---------------------------------------------
__device__ __forceinline__ float fexp(float x) {
    float y = fmaxf(x * 1.4426950408889634f, -126.0f);
    float fl = floorf(y);
    float f = y - fl;
    float p = 1.5403530e-4f;
    p = fmaf(p, f, 1.3333558e-3f);
    p = fmaf(p, f, 9.6181291e-3f);
    p = fmaf(p, f, 5.5504109e-2f);
    p = fmaf(p, f, 2.4022651e-1f);
    p = fmaf(p, f, 6.9314718e-1f);
    p = fmaf(p, f, 1.0f);
    int e = (int)fl;
    return __int_as_float((e + 127) << 23) * p;
}

// ---------------- fused flash attention -------------------------------------
__global__ __launch_bounds__(256) void attn_fused(const __nv_bfloat16* __restrict__ Q3,
                                                  const __nv_bfloat16* __restrict__ K3,
                                                  const __nv_bfloat16* __restrict__ Vt3,
                                                  __half* __restrict__ AT2) {
    int bx = 15 - (int)blockIdx.x;             // longest first
    int h = blockIdx.y, kg = h >> 2;
    extern __shared__ char smraw[];
    Stage* st = (Stage*)smraw;
    int tid = threadIdx.x, wid = tid >> 5, lane = tid & 31;
    int g = lane >> 2, t = lane & 3;

    uint32_t sa[3], sb[3];
#pragma unroll
    for (int s = 0; s < 3; s++) { sa[s] = s2u(st[s].A); sb[s] = s2u(st[s].B); }

    int a_row = wid * 16 + (lane & 15);
    int a_kh  = (lane >> 4) * 8;
    uint32_t a_off = (uint32_t)(a_row * SMS + a_kh) * 2;
    int b_row = (lane & 7) + ((lane >> 4) ? 8 : 0);
    int b_kh  = ((lane >> 3) & 1) * 8;
    uint32_t b_off = (uint32_t)(b_row * SMS + b_kh) * 2;

    const __nv_bfloat16* Qb = Q3 + (size_t)bx * 128 * K3DIM + h * K3HD;
    const int ldK = NKV * K3HD;
    const __nv_bfloat16* Kb = K3 + (size_t)kg * K3HD;
    const __nv_bfloat16* Vb = Vt3 + (size_t)kg * 128 * K3S;

    float m0 = -CUDART_INF_F, m1 = -CUDART_INF_F, l0 = 0.f, l1 = 0.f;
    float o[16][4];
#pragma unroll
    for (int dj = 0; dj < 16; dj++) { o[dj][0] = o[dj][1] = o[dj][2] = o[dj][3] = 0.f; }

    const float scale = 0.088388347648318447f;   // 1/sqrt(128)
    int row0 = bx * 128 + wid * 16 + g;
    int row1 = row0 + 8;

    for (int by = 0; by <= bx; by++) {
        // ---------- S = Q K^T (3-stage, 1 sync/chunk) ----------
        float acc[16][4] = {};
        const __nv_bfloat16* Kt = Kb + (size_t)by * 128 * ldK;
        issue_tile(sa[0], sb[0], Qb, K3DIM, Kt, ldK, 0, tid);
        issue_tile(sa[1], sb[1], Qb, K3DIM, Kt, ldK, BK, tid);
        for (int c = 0; c < 12; c++) {
            cpa_wait(c + 1 < 12);
            __syncthreads();
            if (c + 2 < 12)
                issue_tile(sa[(c + 2) % 3], sb[(c + 2) % 3], Qb, K3DIM, Kt, ldK, (c + 2) * BK, tid);
            uint32_t Au = sa[c % 3], Bu = sb[c % 3];
#pragma unroll
            for (int ks = 0; ks < BK; ks += 16) {
                uint32_t af[4], bf[16][2];
                ldsm4(af[0], af[1], af[2], af[3], Au + a_off + ks * 2);
#pragma unroll
                for (int njp = 0; njp < 8; njp++)
                    ldsm4(bf[2 * njp][0], bf[2 * njp][1], bf[2 * njp + 1][0], bf[2 * njp + 1][1],
                          Bu + b_off + ks * 2 + njp * 16 * SMS * 2);
#pragma unroll
                for (int nj = 0; nj < 16; nj++)
                    mma_bf16(acc[nj], af, bf[nj]);
            }
        }
        __syncthreads();
        // ---------- online softmax (registers only) ----------
        bool diag = (by == bx);
        float rx0 = -CUDART_INF_F, rx1 = -CUDART_INF_F;
#pragma unroll
        for (int nj = 0; nj < 16; nj++) {
            int col = by * 128 + nj * 8 + 2 * t;
            float v0 = acc[nj][0] * scale, v1 = acc[nj][1] * scale;
            float v2 = acc[nj][2] * scale, v3 = acc[nj][3] * scale;
            if (diag) {
                if (col     > row0) v0 = -CUDART_INF_F;
                if (col + 1 > row0) v1 = -CUDART_INF_F;
                if (col     > row1) v2 = -CUDART_INF_F;
                if (col + 1 > row1) v3 = -CUDART_INF_F;
            }
            acc[nj][0] = v0; acc[nj][1] = v1; acc[nj][2] = v2; acc[nj][3] = v3;
            rx0 = fmaxf(rx0, fmaxf(v0, v1)); rx1 = fmaxf(rx1, fmaxf(v2, v3));
        }
        rx0 = fmaxf(rx0, __shfl_xor_sync(~0u, rx0, 1));
        rx0 = fmaxf(rx0, __shfl_xor_sync(~0u, rx0, 2));
        rx1 = fmaxf(rx1, __shfl_xor_sync(~0u, rx1, 1));
        rx1 = fmaxf(rx1, __shfl_xor_sync(~0u, rx1, 2));
        float mn0 = fmaxf(m0, rx0), mn1 = fmaxf(m1, rx1);
        float al0 = fexp(m0 - mn0), al1 = fexp(m1 - mn1);
        m0 = mn0; m1 = mn1;
        float rs0 = 0.f, rs1 = 0.f;
        uint32_t ph[16][2], pl[16][2];
#pragma unroll
        for (int nj = 0; nj < 16; nj++) {
            float p0 = fexp(acc[nj][0] - mn0), p1 = fexp(acc[nj][1] - mn0);
            float p2 = fexp(acc[nj][2] - mn1), p3 = fexp(acc[nj][3] - mn1);
            rs0 += p0 + p1; rs1 += p2 + p3;
            __nv_bfloat16 h0, q0, h1, q1, h2, q2, h3, q3;
            split2(p0, h0, q0); split2(p1, h1, q1);
            split2(p2, h2, q2); split2(p3, h3, q3);
            __nv_bfloat162 a01; a01.x = h0; a01.y = h1;
            __nv_bfloat162 a23; a23.x = h2; a23.y = h3;
            __nv_bfloat162 b01; b01.x = q0; b01.y = q1;
            __nv_bfloat162 b23; b23.x = q2; b23.y = q3;
            ph[nj][0] = *(uint32_t*)&a01; ph[nj][1] = *(uint32_t*)&a23;
            pl[nj][0] = *(uint32_t*)&b01; pl[nj][1] = *(uint32_t*)&b23;
        }
        rs0 += __shfl_xor_sync(~0u, rs0, 1); rs0 += __shfl_xor_sync(~0u, rs0, 2);
        rs1 += __shfl_xor_sync(~0u, rs1, 1); rs1 += __shfl_xor_sync(~0u, rs1, 2);
        l0 = l0 * al0 + rs0; l1 = l1 * al1 + rs1;
#pragma unroll
        for (int dj = 0; dj < 16; dj++) {
            o[dj][0] *= al0; o[dj][1] *= al0; o[dj][2] *= al1; o[dj][3] *= al1;
        }
        // ---------- O += P @ V^T (3-stage, 1 sync/chunk) ----------
        const __nv_bfloat16* Vt = Vb + (size_t)by * 384;
        issue_tile_b(sb[0], Vt, K3S, 0, tid);
        issue_tile_b(sb[1], Vt, K3S, BK, tid);
        for (int c = 0; c < 12; c++) {
            cpa_wait(c + 1 < 12);
            __syncthreads();
            if (c + 2 < 12)
                issue_tile_b(sb[(c + 2) % 3], Vt, K3S, (c + 2) * BK, tid);
            uint32_t Bu = sb[c % 3];
#pragma unroll
            for (int ks = 0; ks < BK; ks += 16) {
                int kk  = c * 2 + (ks >> 4);         // tripled k16 index 0..23
                int b64 = kk >> 2;
                int sel = b64 % 3;                   // 0:hi 1:lo 2:hi
                int j16 = (b64 / 3) * 4 + (kk & 3);  // kv 16-chunk 0..7
                uint32_t af[4];
                if (sel == 1) {
                    af[0] = pl[2 * j16][0]; af[1] = pl[2 * j16][1];
                    af[2] = pl[2 * j16 + 1][0]; af[3] = pl[2 * j16 + 1][1];
                } else {
                    af[0] = ph[2 * j16][0]; af[1] = ph[2 * j16][1];
                    af[2] = ph[2 * j16 + 1][0]; af[3] = ph[2 * j16 + 1][1];
                }
                uint32_t bf[16][2];
#pragma unroll
                for (int njp = 0; njp < 8; njp++)
                    ldsm4(bf[2 * njp][0], bf[2 * njp][1], bf[2 * njp + 1][0], bf[2 * njp + 1][1],
                          Bu + b_off + ks * 2 + njp * 16 * SMS * 2);
#pragma unroll
                for (int dj = 0; dj < 16; dj++)
                    mma_bf16(o[dj], af, bf[dj]);
            }
        }
        __syncthreads();
    }
    // ---------- epilogue: O/l -> fp16 [hi,lo] at2 ----------
    float inv0 = __fdividef(1.f, l0), inv1 = __fdividef(1.f, l1);
#pragma unroll
    for (int dj = 0; dj < 16; dj++) {
        int d = h * 128 + dj * 8 + 2 * t;
        size_t kb = (size_t)(d >> 5) * 64 + (d & 31);
        float v0 = o[dj][0] * inv0, v1 = o[dj][1] * inv0;
        float v2 = o[dj][2] * inv1, v3 = o[dj][3] * inv1;
        __half h0 = __float2half(v0), h1 = __float2half(v1);
        __half h2 = __float2half(v2), h3 = __float2half(v3);
        __half e0 = __float2half(v0 - __half2float(h0));
        __half e1 = __float2half(v1 - __half2float(h1));
        __half e2 = __float2half(v2 - __half2float(h2));
        __half e3 = __float2half(v3 - __half2float(h3));
        __half2 hp0; hp0.x = h0; hp0.y = h1;
        __half2 lp0; lp0.x = e0; lp0.y = e1;
        __half2 hp1; hp1.x = h2; hp1.y = h3;
        __half2 lp1; lp1.x = e2; lp1.y = e3;
        __half* p0 = AT2 + (size_t)row0 * K2DIM + kb;
        __half* p1 = AT2 + (size_t)row1 * K2DIM + kb;
        *(__half2*)(p0) = hp0; *(__half2*)(p0 + 32) = lp0;
        *(__half2*)(p1) = hp1; *(__half2*)(p1 + 32) = lp1;
    }
}

// ---------------- conversion kernels ----------------------------------------
__global__ void conv_a3(const float* __restrict__ W, __nv_bfloat16* __restrict__ W3, int total2) {
    int idx = blockIdx.x * 256 + threadIdx.x;
    if (idx >= total2) return;
    int k = (idx & 2047) * 2, m = idx >> 11;
    float2 w = *(const float2*)(W + (size_t)m * 4096 + k);
    __nv_bfloat16 h0, l0, h1, l1;
    split2(w.x, h0, l0); split2(w.y, h1, l1);
    __nv_bfloat162 hp; hp.x = h0; hp.y = h1;
    __nv_bfloat162 lp; lp.x = l0; lp.y = l1;
    size_t base = (size_t)m * K3DIM + (size_t)(k >> 6) * 192 + (k & 63);
    *(__nv_bfloat162*)(W3 + base)       = hp;
    *(__nv_bfloat162*)(W3 + base + 64)  = lp;
    *(__nv_bfloat162*)(W3 + base + 128) = hp;
}
__global__ void conv_b3(const float* __restrict__ W, __nv_bfloat16* __restrict__ W3, int total2) {
    int idx = blockIdx.x * 256 + threadIdx.x;
    if (idx >= total2) return;
    int k = (idx & 2047) * 2, m = idx >> 11;
    float2 w = *(const float2*)(W + (size_t)m * 4096 + k);
    __nv_bfloat16 h0, l0, h1, l1;
    split2(w.x, h0, l0); split2(w.y, h1, l1);
    __nv_bfloat162 hp; hp.x = h0; hp.y = h1;
    __nv_bfloat162 lp; lp.x = l0; lp.y = l1;
    size_t base = (size_t)m * K3DIM + (size_t)(k >> 6) * 192 + (k & 63);
    *(__nv_bfloat162*)(W3 + base)       = hp;
    *(__nv_bfloat162*)(W3 + base + 64)  = hp;
    *(__nv_bfloat162*)(W3 + base + 128) = lp;
}
__global__ void conv_wo2(const float* __restrict__ W, __half* __restrict__ W2, int total2) {
    int idx = blockIdx.x * 256 + threadIdx.x;
    if (idx >= total2) return;
    int k = (idx & 2047) * 2, m = idx >> 11;
    float2 w = *(const float2*)(W + (size_t)m * 4096 + k);
    __half2 hp; hp.x = __float2half(w.x); hp.y = __float2half(w.y);
    size_t base = (size_t)m * K2DIM + (size_t)(k >> 5) * 64 + (k & 31);
    *(__half2*)(W2 + base)      = hp;
    *(__half2*)(W2 + base + 32) = hp;
}

__global__ void rope_conv_q(const float* __restrict__ Q, const float* __restrict__ fc,
                            const float* __restrict__ fs, __nv_bfloat16* __restrict__ Q3) {
    int idx = blockIdx.x * 256 + threadIdx.x;           // S*NH*64
    int i = idx & 63, h = (idx >> 6) & 31, s = idx >> 11;
    float c = fc[(s << 6) + i], sn = fs[(s << 6) + i];
    const float* qp = Q + (size_t)s * DIM + h * HD + 2 * i;
    float xr = qp[0], xi = qp[1];
    float vr = xr * c - xi * sn, vi = xr * sn + xi * c;
    int d0 = 2 * i;
    size_t base = (size_t)s * K3DIM + h * K3HD + (size_t)(d0 >> 6) * 192 + (d0 & 63);
    __nv_bfloat16 hr, lr, hi_, li;
    split2(vr, hr, lr); split2(vi, hi_, li);
    __nv_bfloat162 hp; hp.x = hr; hp.y = hi_;
    __nv_bfloat162 lp; lp.x = lr; lp.y = li;
    *(__nv_bfloat162*)(Q3 + base)       = hp;  // A-pattern
    *(__nv_bfloat162*)(Q3 + base + 64)  = lp;
    *(__nv_bfloat162*)(Q3 + base + 128) = hp;
}
__global__ void rope_conv_k(const float* __restrict__ K, const float* __restrict__ fc,
                            const float* __restrict__ fs, __nv_bfloat16* __restrict__ K3) {
    int idx = blockIdx.x * 256 + threadIdx.x;           // S*NKV*64
    int i = idx & 63, h = (idx >> 6) & 7, s = idx >> 9;
    float c = fc[(s << 6) + i], sn = fs[(s << 6) + i];
    const float* kp = K + (size_t)s * KV_DIM + h * HD + 2 * i;
    float xr = kp[0], xi = kp[1];
    float vr = xr * c - xi * sn, vi = xr * sn + xi * c;
    int d0 = 2 * i;
    size_t base = (size_t)s * (NKV * K3HD) + h * K3HD + (size_t)(d0 >> 6) * 192 + (d0 & 63);
    __nv_bfloat16 hr, lr, hi_, li;
    split2(vr, hr, lr); split2(vi, hi_, li);
    __nv_bfloat162 hp; hp.x = hr; hp.y = hi_;
    __nv_bfloat162 lp; lp.x = lr; lp.y = li;
    *(__nv_bfloat162*)(K3 + base)       = hp;  // B-pattern
    *(__nv_bfloat162*)(K3 + base + 64)  = hp;
    *(__nv_bfloat162*)(K3 + base + 128) = lp;
}
__global__ void conv_vt(const float* __restrict__ V, __nv_bfloat16* __restrict__ Vt3) {
    __shared__ float t[32][33];
    int s0 = blockIdx.x * 32, d0 = blockIdx.y * 32;
    int tx = threadIdx.x, ty = threadIdx.y;
#pragma unroll
    for (int i = 0; i < 32; i += 8)
        t[ty + i][tx] = V[(size_t)(s0 + ty + i) * KV_DIM + d0 + tx];
    __syncthreads();
#pragma unroll
    for (int i = 0; i < 32; i += 8) {
        int d = d0 + ty + i, s = s0 + tx;
        __nv_bfloat16 hi, lo;
        split2(t[tx][ty + i], hi, lo);
        size_t base = (size_t)d * K3S + (size_t)(s >> 6) * 192 + (s & 63);
        Vt3[base] = hi; Vt3[base + 64] = hi; Vt3[base + 128] = lo;
    }
}

// ---------------- launch ----------------------------------------------------
extern "C" void kernel_launch(void* const* d_in, const int* in_sizes, int n_in,
                              void* d_out, int out_size) {
    const float* x  = (const float*)d_in[0];
    const float* wq = (const float*)d_in[1];
    const float* wk = (const float*)d_in[2];
    const float* wv = (const float*)d_in[3];
    const float* wo = (const float*)d_in[4];
    const float* fc = (const float*)d_in[5];
    const float* fs = (const float*)d_in[6];
    float* out = (float*)d_out;

    float *Q, *K, *V;
    __nv_bfloat16 *x3, *wq3, *wk3, *wv3, *q3, *k3, *vt3;
    __half *at2, *wo2;
    cudaGetSymbolAddress((void**)&Q,   g_q);
    cudaGetSymbolAddress((void**)&K,   g_k);
    cudaGetSymbolAddress((void**)&V,   g_v);
    cudaGetSymbolAddress((void**)&x3,  g_x3);
    cudaGetSymbolAddress((void**)&wq3, g_wq3);
    cudaGetSymbolAddress((void**)&wk3, g_wk3);
    cudaGetSymbolAddress((void**)&wv3, g_wv3);
    cudaGetSymbolAddress((void**)&q3,  g_q3);
    cudaGetSymbolAddress((void**)&k3,  g_k3);
    cudaGetSymbolAddress((void**)&vt3, g_vt3);
    cudaGetSymbolAddress((void**)&at2, g_at2);
    cudaGetSymbolAddress((void**)&wo2, g_wo2);

    cudaFuncSetAttribute(gemm_f32_k<false>, cudaFuncAttributeMaxDynamicSharedMemorySize, SMEM_BYTES);
    cudaFuncSetAttribute(gemm_f32_k<true>,  cudaFuncAttributeMaxDynamicSharedMemorySize, SMEM_BYTES);
    cudaFuncSetAttribute(attn_fused,        cudaFuncAttributeMaxDynamicSharedMemorySize, SMEM_BYTES);

    // operand splitting
    conv_a3<<<(S_LEN * DIM / 2 + 255) / 256, 256>>>(x,  x3,  S_LEN * DIM / 2);
    conv_b3<<<(DIM * DIM / 2 + 255) / 256, 256>>>(wq, wq3, DIM * DIM / 2);
    conv_b3<<<(KV_DIM * DIM / 2 + 255) / 256, 256>>>(wk, wk3, KV_DIM * DIM / 2);
    conv_b3<<<(KV_DIM * DIM / 2 + 255) / 256, 256>>>(wv, wv3, KV_DIM * DIM / 2);
    conv_wo2<<<(DIM * DIM / 2 + 255) / 256, 256>>>(wo, wo2, DIM * DIM / 2);

    // QKV projections (bf16 3-split)
    gemm_f32_k<false><<<dim3(16, 32), 256, SMEM_BYTES>>>(x3, K3DIM, wq3, K3DIM, Q, DIM,    K3DIM / BK);
    gemm_f32_k<false><<<dim3(16,  8), 256, SMEM_BYTES>>>(x3, K3DIM, wk3, K3DIM, K, KV_DIM, K3DIM / BK);
    gemm_f32_k<false><<<dim3(16,  8), 256, SMEM_BYTES>>>(x3, K3DIM, wv3, K3DIM, V, KV_DIM, K3DIM / BK);

    // RoPE + split (fused)
    rope_conv_q<<<(S_LEN * NH  * 64) / 256, 256>>>(Q, fc, fs, q3);
    rope_conv_k<<<(S_LEN * NKV * 64) / 256, 256>>>(K, fc, fs, k3);
    conv_vt<<<dim3(S_LEN / 32, KV_DIM / 32), dim3(32, 8)>>>(V, vt3);

    // fused attention (score + softmax + PV), writes fp16 [hi,lo] at2
    attn_fused<<<dim3(16, NH), 256, SMEM_BYTES>>>(q3, k3, vt3, at2);

    // output projection (fp16 2-split)
    gemm_f32_k<true><<<dim3(16, 32), 256, SMEM_BYTES>>>(
        (const __nv_bfloat16*)at2, K2DIM, (const __nv_bfloat16*)wo2, K2DIM, out, DIM, K2DIM / BK);
}

// round 14
// speedup vs baseline: 3.0630x; 1.2588x over previous
#include <cuda_runtime.h>
#include <cuda_bf16.h>
#include <cuda_fp16.h>
#include <math_constants.h>
#include <cstdint>

#define S_LEN  2048
#define DIM    4096
#define KV_DIM 1024
#define NH     32
#define NKV    8
#define HD     128
#define K2DIM  8192       // 2*4096 (doubled K: fp16 2-split, QKV + WO)
#define K3HD   384        // 3*128  (tripled K for scores, bf16 3-split)
#define K2S    4096       // 2*2048 (doubled K for PV, fp16 2-split)
#define K3DIM  12288      // stride of q3 rows (3*4096)
#define BK     32
#define SMS    40         // smem row stride in 16-bit elems (32 + 8 pad; 80B)

// ---------------- scratch (module-load allocated) ---------------------------
__device__ __align__(16) float g_q[S_LEN * DIM];
__device__ __align__(16) float g_k[S_LEN * KV_DIM];
__device__ __align__(16) float g_v[S_LEN * KV_DIM];
__device__ __align__(16) __half        g_x2 [S_LEN * K2DIM];             // x,   fp16 [hi,lo]
__device__ __align__(16) __half        g_wq2[DIM * K2DIM];               // fp16 [hi,hi]
__device__ __align__(16) __half        g_wk2[KV_DIM * K2DIM];
__device__ __align__(16) __half        g_wv2[KV_DIM * K2DIM];
__device__ __align__(16) __half        g_wo2[DIM * K2DIM];
__device__ __align__(16) __nv_bfloat16 g_q3 [S_LEN * K3DIM];             // roped, bf16 A-pat
__device__ __align__(16) __nv_bfloat16 g_k3 [S_LEN * (NKV * K3HD)];      // roped, bf16 B-pat
__device__ __align__(16) __half        g_vt2[KV_DIM * K2S];              // V^T, fp16 [hi,hi]
__device__ __align__(16) __half        g_at2[S_LEN * K2DIM];             // attn out, fp16 [hi,lo]

// ---------------- helpers ----------------------------------------------------
__device__ __forceinline__ void split2(float a, __nv_bfloat16& hi, __nv_bfloat16& lo) {
    hi = __float2bfloat16(a);
    lo = __float2bfloat16(a - __bfloat162float(hi));
}
__device__ __forceinline__ void split2h(float a, __half& hi, __half& lo) {
    hi = __float2half(a);
    lo = __float2half(a - __half2float(hi));
}
__device__ __forceinline__ uint32_t s2u(const void* p) {
    uint32_t a;
    asm("{ .reg .u64 t; cvta.to.shared.u64 t, %1; cvt.u32.u64 %0, t; }" : "=r"(a) : "l"(p));
    return a;
}
__device__ __forceinline__ void cpa16(uint32_t s, const void* g) {
    asm volatile("cp.async.cg.shared.global [%0], [%1], 16;" :: "r"(s), "l"(g));
}
__device__ __forceinline__ void cpa_commit() {
    asm volatile("cp.async.commit_group;" ::: "memory");
}
__device__ __forceinline__ void cpa_wait(int more) {
    if (more) asm volatile("cp.async.wait_group 1;" ::: "memory");
    else      asm volatile("cp.async.wait_group 0;" ::: "memory");
}
__device__ __forceinline__ void mma_bf16(float* c, const uint32_t* a, const uint32_t* b) {
    asm volatile(
        "mma.sync.aligned.m16n8k16.row.col.f32.bf16.bf16.f32 "
        "{%0,%1,%2,%3}, {%4,%5,%6,%7}, {%8,%9}, {%0,%1,%2,%3};"
        : "+f"(c[0]), "+f"(c[1]), "+f"(c[2]), "+f"(c[3])
        : "r"(a[0]), "r"(a[1]), "r"(a[2]), "r"(a[3]), "r"(b[0]), "r"(b[1]));
}
__device__ __forceinline__ void mma_f16(float* c, const uint32_t* a, const uint32_t* b) {
    asm volatile(
        "mma.sync.aligned.m16n8k16.row.col.f32.f16.f16.f32 "
        "{%0,%1,%2,%3}, {%4,%5,%6,%7}, {%8,%9}, {%0,%1,%2,%3};"
        : "+f"(c[0]), "+f"(c[1]), "+f"(c[2]), "+f"(c[3])
        : "r"(a[0]), "r"(a[1]), "r"(a[2]), "r"(a[3]), "r"(b[0]), "r"(b[1]));
}
__device__ __forceinline__ void ldsm4(uint32_t& r0, uint32_t& r1, uint32_t& r2, uint32_t& r3,
                                      uint32_t addr) {
    asm volatile("ldmatrix.sync.aligned.m8n8.x4.shared.b16 {%0,%1,%2,%3}, [%4];"
                 : "=r"(r0), "=r"(r1), "=r"(r2), "=r"(r3) : "r"(addr));
}

// ---------------- 3-stage pipelined GEMM core -------------------------------
struct Stage {
    __align__(16) __nv_bfloat16 A[128 * SMS];
    __align__(16) __nv_bfloat16 B[128 * SMS];
};
#define SMEM_BYTES (3 * (int)sizeof(Stage))

__device__ __forceinline__ void issue_tile(uint32_t sa, uint32_t sb,
                                           const __nv_bfloat16* __restrict__ A3, int lda3,
                                           const __nv_bfloat16* __restrict__ B3, int ldb3,
                                           int k0, int tid) {
#pragma unroll
    for (int i = 0; i < 2; i++) {
        int idx = i * 256 + tid;
        int r = idx >> 2, c = idx & 3;
        cpa16(sa + (r * SMS + c * 8) * 2, A3 + (size_t)r * lda3 + k0 + c * 8);
    }
#pragma unroll
    for (int i = 0; i < 2; i++) {
        int idx = i * 256 + tid;
        int r = idx >> 2, c = idx & 3;
        cpa16(sb + (r * SMS + c * 8) * 2, B3 + (size_t)r * ldb3 + k0 + c * 8);
    }
    cpa_commit();
}
__device__ __forceinline__ void issue_tile_b(uint32_t sb,
                                             const __nv_bfloat16* __restrict__ B3, int ldb3,
                                             int k0, int tid) {
#pragma unroll
    for (int i = 0; i < 2; i++) {
        int idx = i * 256 + tid;
        int r = idx >> 2, c = idx & 3;
        cpa16(sb + (r * SMS + c * 8) * 2, B3 + (size_t)r * ldb3 + k0 + c * 8);
    }
    cpa_commit();
}

template <bool F16>
__device__ __forceinline__ void gemm_main(const __nv_bfloat16* __restrict__ A3, int lda3,
                                          const __nv_bfloat16* __restrict__ B3, int ldb3,
                                          int nchunks, Stage* st, float (&acc)[4][4][4]) {
    int tid = threadIdx.x, wid = tid >> 5, lane = tid & 31;
    int wm = (wid & 1) * 64, wn = (wid >> 1) * 32;
    uint32_t sa[3], sb[3];
#pragma unroll
    for (int s = 0; s < 3; s++) { sa[s] = s2u(st[s].A); sb[s] = s2u(st[s].B); }

    int a_row = wm + (lane & 15);
    int a_kh  = (lane >> 4) * 8;
    int b_row = wn + (lane & 7) + ((lane >> 4) ? 8 : 0);
    int b_kh  = ((lane >> 3) & 1) * 8;
    uint32_t a_off = (uint32_t)(a_row * SMS + a_kh) * 2;
    uint32_t b_off = (uint32_t)(b_row * SMS + b_kh) * 2;

    issue_tile(sa[0], sb[0], A3, lda3, B3, ldb3, 0, tid);
    if (nchunks > 1) issue_tile(sa[1], sb[1], A3, lda3, B3, ldb3, BK, tid);

    for (int c = 0; c < nchunks; c++) {
        cpa_wait(c + 1 < nchunks);
        __syncthreads();
        if (c + 2 < nchunks)
            issue_tile(sa[(c + 2) % 3], sb[(c + 2) % 3], A3, lda3, B3, ldb3, (c + 2) * BK, tid);
        uint32_t Au = sa[c % 3], Bu = sb[c % 3];
#pragma unroll
        for (int ks = 0; ks < BK; ks += 16) {
            uint32_t af[4][4], bf[4][2];
            uint32_t aa = Au + a_off + ks * 2;
            uint32_t ba = Bu + b_off + ks * 2;
#pragma unroll
            for (int mi = 0; mi < 4; mi++)
                ldsm4(af[mi][0], af[mi][1], af[mi][2], af[mi][3], aa + mi * 16 * SMS * 2);
#pragma unroll
            for (int njp = 0; njp < 2; njp++)
                ldsm4(bf[2 * njp][0], bf[2 * njp][1], bf[2 * njp + 1][0], bf[2 * njp + 1][1],
                      ba + njp * 16 * SMS * 2);
#pragma unroll
            for (int mi = 0; mi < 4; mi++)
#pragma unroll
                for (int nj = 0; nj < 4; nj++) {
                    if (F16) mma_f16(acc[mi][nj], af[mi], bf[nj]);
                    else     mma_bf16(acc[mi][nj], af[mi], bf[nj]);
                }
        }
    }
    __syncthreads();
}

template <bool F16>
__global__ __launch_bounds__(256) void gemm_f32_k(const __nv_bfloat16* __restrict__ A3, int lda3,
                                                  const __nv_bfloat16* __restrict__ B3, int ldb3,
                                                  float* __restrict__ C, int ldc, int nchunks) {
    extern __shared__ char smraw[];
    Stage* st = (Stage*)smraw;
    float acc[4][4][4] = {};
    gemm_main<F16>(A3 + (size_t)blockIdx.x * 128 * lda3, lda3,
                   B3 + (size_t)blockIdx.y * 128 * ldb3, ldb3, nchunks, st, acc);
    int tid = threadIdx.x, wid = tid >> 5, lane = tid & 31;
    int wm = (wid & 1) * 64, wn = (wid >> 1) * 32;
    int g = lane >> 2, t = lane & 3;
#pragma unroll
    for (int mi = 0; mi < 4; mi++)
#pragma unroll
        for (int nj = 0; nj < 4; nj++) {
            int r0 = blockIdx.x * 128 + wm + mi * 16 + g;
            int c0 = blockIdx.y * 128 + wn + nj * 8 + t * 2;
            *(float2*)(C + (size_t)r0 * ldc + c0)       = make_float2(acc[mi][nj][0], acc[mi][nj][1]);
            *(float2*)(C + (size_t)(r0 + 8) * ldc + c0) = make_float2(acc[mi][nj][2], acc[mi][nj][3]);
        }
}

// ---------------- FFMA-only exp ---------------------------------------------
__device__ __forceinline__ float fexp(float x) {
    float y = fmaxf(x * 1.4426950408889634f, -126.0f);
    float fl = floorf(y);
    float f = y - fl;
    float p = 1.5403530e-4f;
    p = fmaf(p, f, 1.3333558e-3f);
    p = fmaf(p, f, 9.6181291e-3f);
    p = fmaf(p, f, 5.5504109e-2f);
    p = fmaf(p, f, 2.4022651e-1f);
    p = fmaf(p, f, 6.9314718e-1f);
    p = fmaf(p, f, 1.0f);
    int e = (int)fl;
    return __int_as_float((e + 127) << 23) * p;
}

// ---------------- fused flash attention -------------------------------------
// Scores: bf16 3-split (12 chunks).  PV: fp16 2-split (8 chunks).
__global__ __launch_bounds__(256) void attn_fused(const __nv_bfloat16* __restrict__ Q3,
                                                  const __nv_bfloat16* __restrict__ K3,
                                                  const __half* __restrict__ Vt2,
                                                  __half* __restrict__ AT2) {
    int bx = 15 - (int)blockIdx.x;             // longest first
    int h = blockIdx.y, kg = h >> 2;
    extern __shared__ char smraw[];
    Stage* st = (Stage*)smraw;
    int tid = threadIdx.x, wid = tid >> 5, lane = tid & 31;
    int g = lane >> 2, t = lane & 3;

    uint32_t sa[3], sb[3];
#pragma unroll
    for (int s = 0; s < 3; s++) { sa[s] = s2u(st[s].A); sb[s] = s2u(st[s].B); }

    int a_row = wid * 16 + (lane & 15);
    int a_kh  = (lane >> 4) * 8;
    uint32_t a_off = (uint32_t)(a_row * SMS + a_kh) * 2;
    int b_row = (lane & 7) + ((lane >> 4) ? 8 : 0);
    int b_kh  = ((lane >> 3) & 1) * 8;
    uint32_t b_off = (uint32_t)(b_row * SMS + b_kh) * 2;

    const __nv_bfloat16* Qb = Q3 + (size_t)bx * 128 * K3DIM + h * K3HD;
    const int ldK = NKV * K3HD;
    const __nv_bfloat16* Kb = K3 + (size_t)kg * K3HD;
    const __nv_bfloat16* Vb = (const __nv_bfloat16*)(Vt2 + (size_t)kg * 128 * K2S);

    float m0 = -CUDART_INF_F, m1 = -CUDART_INF_F, l0 = 0.f, l1 = 0.f;
    float o[16][4];
#pragma unroll
    for (int dj = 0; dj < 16; dj++) { o[dj][0] = o[dj][1] = o[dj][2] = o[dj][3] = 0.f; }

    const float scale = 0.088388347648318447f;   // 1/sqrt(128)
    int row0 = bx * 128 + wid * 16 + g;
    int row1 = row0 + 8;

    for (int by = 0; by <= bx; by++) {
        // ---------- S = Q K^T (bf16 3-split, 12 chunks) ----------
        float acc[16][4] = {};
        const __nv_bfloat16* Kt = Kb + (size_t)by * 128 * ldK;
        issue_tile(sa[0], sb[0], Qb, K3DIM, Kt, ldK, 0, tid);
        issue_tile(sa[1], sb[1], Qb, K3DIM, Kt, ldK, BK, tid);
        for (int c = 0; c < 12; c++) {
            cpa_wait(c + 1 < 12);
            __syncthreads();
            if (c + 2 < 12)
                issue_tile(sa[(c + 2) % 3], sb[(c + 2) % 3], Qb, K3DIM, Kt, ldK, (c + 2) * BK, tid);
            uint32_t Au = sa[c % 3], Bu = sb[c % 3];
#pragma unroll
            for (int ks = 0; ks < BK; ks += 16) {
                uint32_t af[4], bf[16][2];
                ldsm4(af[0], af[1], af[2], af[3], Au + a_off + ks * 2);
#pragma unroll
                for (int njp = 0; njp < 8; njp++)
                    ldsm4(bf[2 * njp][0], bf[2 * njp][1], bf[2 * njp + 1][0], bf[2 * njp + 1][1],
                          Bu + b_off + ks * 2 + njp * 16 * SMS * 2);
#pragma unroll
                for (int nj = 0; nj < 16; nj++)
                    mma_bf16(acc[nj], af, bf[nj]);
            }
        }
        __syncthreads();
        // ---------- online softmax (registers only) ----------
        bool diag = (by == bx);
        float rx0 = -CUDART_INF_F, rx1 = -CUDART_INF_F;
#pragma unroll
        for (int nj = 0; nj < 16; nj++) {
            int col = by * 128 + nj * 8 + 2 * t;
            float v0 = acc[nj][0] * scale, v1 = acc[nj][1] * scale;
            float v2 = acc[nj][2] * scale, v3 = acc[nj][3] * scale;
            if (diag) {
                if (col     > row0) v0 = -CUDART_INF_F;
                if (col + 1 > row0) v1 = -CUDART_INF_F;
                if (col     > row1) v2 = -CUDART_INF_F;
                if (col + 1 > row1) v3 = -CUDART_INF_F;
            }
            acc[nj][0] = v0; acc[nj][1] = v1; acc[nj][2] = v2; acc[nj][3] = v3;
            rx0 = fmaxf(rx0, fmaxf(v0, v1)); rx1 = fmaxf(rx1, fmaxf(v2, v3));
        }
        rx0 = fmaxf(rx0, __shfl_xor_sync(~0u, rx0, 1));
        rx0 = fmaxf(rx0, __shfl_xor_sync(~0u, rx0, 2));
        rx1 = fmaxf(rx1, __shfl_xor_sync(~0u, rx1, 1));
        rx1 = fmaxf(rx1, __shfl_xor_sync(~0u, rx1, 2));
        float mn0 = fmaxf(m0, rx0), mn1 = fmaxf(m1, rx1);
        float al0 = fexp(m0 - mn0), al1 = fexp(m1 - mn1);
        m0 = mn0; m1 = mn1;
        float rs0 = 0.f, rs1 = 0.f;
        uint32_t ph[16][2], pl[16][2];     // fp16 hi/lo A-fragments of P
#pragma unroll
        for (int nj = 0; nj < 16; nj++) {
            float p0 = fexp(acc[nj][0] - mn0), p1 = fexp(acc[nj][1] - mn0);
            float p2 = fexp(acc[nj][2] - mn1), p3 = fexp(acc[nj][3] - mn1);
            rs0 += p0 + p1; rs1 += p2 + p3;
            __half h0, q0, h1, q1, h2, q2, h3, q3;
            split2h(p0, h0, q0); split2h(p1, h1, q1);
            split2h(p2, h2, q2); split2h(p3, h3, q3);
            __half2 a01; a01.x = h0; a01.y = h1;
            __half2 a23; a23.x = h2; a23.y = h3;
            __half2 b01; b01.x = q0; b01.y = q1;
            __half2 b23; b23.x = q2; b23.y = q3;
            ph[nj][0] = *(uint32_t*)&a01; ph[nj][1] = *(uint32_t*)&a23;
            pl[nj][0] = *(uint32_t*)&b01; pl[nj][1] = *(uint32_t*)&b23;
        }
        rs0 += __shfl_xor_sync(~0u, rs0, 1); rs0 += __shfl_xor_sync(~0u, rs0, 2);
        rs1 += __shfl_xor_sync(~0u, rs1, 1); rs1 += __shfl_xor_sync(~0u, rs1, 2);
        l0 = l0 * al0 + rs0; l1 = l1 * al1 + rs1;
#pragma unroll
        for (int dj = 0; dj < 16; dj++) {
            o[dj][0] *= al0; o[dj][1] *= al0; o[dj][2] *= al1; o[dj][3] *= al1;
        }
        // ---------- O += P @ V^T (fp16 2-split, 8 chunks) ----------
        // doubled K layout per 64-block: A=[ph(32),pl(32)], B=[vh(32),vh(32)]
        const __nv_bfloat16* Vt = Vb + (size_t)by * 256;
        issue_tile_b(sb[0], Vt, K2S, 0, tid);
        issue_tile_b(sb[1], Vt, K2S, BK, tid);
        for (int c = 0; c < 8; c++) {
            cpa_wait(c + 1 < 8);
            __syncthreads();
            if (c + 2 < 8)
                issue_tile_b(sb[(c + 2) % 3], Vt, K2S, (c + 2) * BK, tid);
            uint32_t Bu = sb[c % 3];
#pragma unroll
            for (int ks = 0; ks < BK; ks += 16) {
                int kk  = c * 2 + (ks >> 4);         // doubled k16 index 0..15
                int b64 = kk >> 2;                   // 64-elem superblock 0..3
                int loc = kk & 3;                    // 0,1: hi halves; 2,3: lo halves
                int sel = loc >> 1;
                int j16 = b64 * 2 + (loc & 1);       // kv 16-chunk 0..7
                uint32_t af[4];
                if (sel == 1) {
                    af[0] = pl[2 * j16][0]; af[1] = pl[2 * j16][1];
                    af[2] = pl[2 * j16 + 1][0]; af[3] = pl[2 * j16 + 1][1];
                } else {
                    af[0] = ph[2 * j16][0]; af[1] = ph[2 * j16][1];
                    af[2] = ph[2 * j16 + 1][0]; af[3] = ph[2 * j16 + 1][1];
                }
                uint32_t bf[16][2];
#pragma unroll
                for (int njp = 0; njp < 8; njp++)
                    ldsm4(bf[2 * njp][0], bf[2 * njp][1], bf[2 * njp + 1][0], bf[2 * njp + 1][1],
                          Bu + b_off + ks * 2 + njp * 16 * SMS * 2);
#pragma unroll
                for (int dj = 0; dj < 16; dj++)
                    mma_f16(o[dj], af, bf[dj]);
            }
        }
        __syncthreads();
    }
    // ---------- epilogue: O/l -> fp16 [hi,lo] at2 ----------
    float inv0 = __fdividef(1.f, l0), inv1 = __fdividef(1.f, l1);
#pragma unroll
    for (int dj = 0; dj < 16; dj++) {
        int d = h * 128 + dj * 8 + 2 * t;
        size_t kb = (size_t)(d >> 5) * 64 + (d & 31);
        float v0 = o[dj][0] * inv0, v1 = o[dj][1] * inv0;
        float v2 = o[dj][2] * inv1, v3 = o[dj][3] * inv1;
        __half h0, e0, h1, e1, h2, e2, h3, e3;
        split2h(v0, h0, e0); split2h(v1, h1, e1);
        split2h(v2, h2, e2); split2h(v3, h3, e3);
        __half2 hp0; hp0.x = h0; hp0.y = h1;
        __half2 lp0; lp0.x = e0; lp0.y = e1;
        __half2 hp1; hp1.x = h2; hp1.y = h3;
        __half2 lp1; lp1.x = e2; lp1.y = e3;
        __half* p0 = AT2 + (size_t)row0 * K2DIM + kb;
        __half* p1 = AT2 + (size_t)row1 * K2DIM + kb;
        *(__half2*)(p0) = hp0; *(__half2*)(p0 + 32) = lp0;
        *(__half2*)(p1) = hp1; *(__half2*)(p1 + 32) = lp1;
    }
}

// ---------------- conversion kernels ----------------------------------------
// fp16 A-pat: [hi,lo]  B-pat: [hi,hi]  per 32-elem K block
__global__ void conv_a2(const float* __restrict__ W, __half* __restrict__ W2, int total2) {
    int idx = blockIdx.x * 256 + threadIdx.x;
    if (idx >= total2) return;
    int k = (idx & 2047) * 2, m = idx >> 11;
    float2 w = *(const float2*)(W + (size_t)m * 4096 + k);
    __half h0, l0, h1, l1;
    split2h(w.x, h0, l0); split2h(w.y, h1, l1);
    __half2 hp; hp.x = h0; hp.y = h1;
    __half2 lp; lp.x = l0; lp.y = l1;
    size_t base = (size_t)m * K2DIM + (size_t)(k >> 5) * 64 + (k & 31);
    *(__half2*)(W2 + base)      = hp;
    *(__half2*)(W2 + base + 32) = lp;
}
__global__ void conv_w2(const float* __restrict__ W, __half* __restrict__ W2, int total2) {
    int idx = blockIdx.x * 256 + threadIdx.x;
    if (idx >= total2) return;
    int k = (idx & 2047) * 2, m = idx >> 11;
    float2 w = *(const float2*)(W + (size_t)m * 4096 + k);
    __half2 hp; hp.x = __float2half(w.x); hp.y = __float2half(w.y);
    size_t base = (size_t)m * K2DIM + (size_t)(k >> 5) * 64 + (k & 31);
    *(__half2*)(W2 + base)      = hp;
    *(__half2*)(W2 + base + 32) = hp;
}

__global__ void rope_conv_q(const float* __restrict__ Q, const float* __restrict__ fc,
                            const float* __restrict__ fs, __nv_bfloat16* __restrict__ Q3) {
    int idx = blockIdx.x * 256 + threadIdx.x;           // S*NH*64
    int i = idx & 63, h = (idx >> 6) & 31, s = idx >> 11;
    float c = fc[(s << 6) + i], sn = fs[(s << 6) + i];
    const float* qp = Q + (size_t)s * DIM + h * HD + 2 * i;
    float xr = qp[0], xi = qp[1];
    float vr = xr * c - xi * sn, vi = xr * sn + xi * c;
    int d0 = 2 * i;
    size_t base = (size_t)s * K3DIM + h * K3HD + (size_t)(d0 >> 6) * 192 + (d0 & 63);
    __nv_bfloat16 hr, lr, hi_, li;
    split2(vr, hr, lr); split2(vi, hi_, li);
    __nv_bfloat162 hp; hp.x = hr; hp.y = hi_;
    __nv_bfloat162 lp; lp.x = lr; lp.y = li;
    *(__nv_bfloat162*)(Q3 + base)       = hp;  // A-pattern [hi,lo,hi]
    *(__nv_bfloat162*)(Q3 + base + 64)  = lp;
    *(__nv_bfloat162*)(Q3 + base + 128) = hp;
}
__global__ void rope_conv_k(const float* __restrict__ K, const float* __restrict__ fc,
                            const float* __restrict__ fs, __nv_bfloat16* __restrict__ K3) {
    int idx = blockIdx.x * 256 + threadIdx.x;           // S*NKV*64
    int i = idx & 63, h = (idx >> 6) & 7, s = idx >> 9;
    float c = fc[(s << 6) + i], sn = fs[(s << 6) + i];
    const float* kp = K + (size_t)s * KV_DIM + h * HD + 2 * i;
    float xr = kp[0], xi = kp[1];
    float vr = xr * c - xi * sn, vi = xr * sn + xi * c;
    int d0 = 2 * i;
    size_t base = (size_t)s * (NKV * K3HD) + h * K3HD + (size_t)(d0 >> 6) * 192 + (d0 & 63);
    __nv_bfloat16 hr, lr, hi_, li;
    split2(vr, hr, lr); split2(vi, hi_, li);
    __nv_bfloat162 hp; hp.x = hr; hp.y = hi_;
    __nv_bfloat162 lp; lp.x = lr; lp.y = li;
    *(__nv_bfloat162*)(K3 + base)       = hp;  // B-pattern [hi,hi,lo]
    *(__nv_bfloat162*)(K3 + base + 64)  = hp;
    *(__nv_bfloat162*)(K3 + base + 128) = lp;
}
// V [S][KV_DIM] -> Vt2 [d=1024][2*2048] fp16 B-pattern (smem transpose)
__global__ void conv_vt2(const float* __restrict__ V, __half* __restrict__ Vt2) {
    __shared__ float t[32][33];
    int s0 = blockIdx.x * 32, d0 = blockIdx.y * 32;
    int tx = threadIdx.x, ty = threadIdx.y;
#pragma unroll
    for (int i = 0; i < 32; i += 8)
        t[ty + i][tx] = V[(size_t)(s0 + ty + i) * KV_DIM + d0 + tx];
    __syncthreads();
#pragma unroll
    for (int i = 0; i < 32; i += 8) {
        int d = d0 + ty + i, s = s0 + tx;
        __half hv = __float2half(t[tx][ty + i]);
        size_t base = (size_t)d * K2S + (size_t)(s >> 5) * 64 + (s & 31);
        Vt2[base] = hv; Vt2[base + 32] = hv;
    }
}

// ---------------- launch ----------------------------------------------------
extern "C" void kernel_launch(void* const* d_in, const int* in_sizes, int n_in,
                              void* d_out, int out_size) {
    const float* x  = (const float*)d_in[0];
    const float* wq = (const float*)d_in[1];
    const float* wk = (const float*)d_in[2];
    const float* wv = (const float*)d_in[3];
    const float* wo = (const float*)d_in[4];
    const float* fc = (const float*)d_in[5];
    const float* fs = (const float*)d_in[6];
    float* out = (float*)d_out;

    float *Q, *K, *V;
    __nv_bfloat16 *q3, *k3;
    __half *x2, *wq2, *wk2, *wv2, *wo2, *vt2, *at2;
    cudaGetSymbolAddress((void**)&Q,   g_q);
    cudaGetSymbolAddress((void**)&K,   g_k);
    cudaGetSymbolAddress((void**)&V,   g_v);
    cudaGetSymbolAddress((void**)&x2,  g_x2);
    cudaGetSymbolAddress((void**)&wq2, g_wq2);
    cudaGetSymbolAddress((void**)&wk2, g_wk2);
    cudaGetSymbolAddress((void**)&wv2, g_wv2);
    cudaGetSymbolAddress((void**)&wo2, g_wo2);
    cudaGetSymbolAddress((void**)&q3,  g_q3);
    cudaGetSymbolAddress((void**)&k3,  g_k3);
    cudaGetSymbolAddress((void**)&vt2, g_vt2);
    cudaGetSymbolAddress((void**)&at2, g_at2);

    cudaFuncSetAttribute(gemm_f32_k<false>, cudaFuncAttributeMaxDynamicSharedMemorySize, SMEM_BYTES);
    cudaFuncSetAttribute(gemm_f32_k<true>,  cudaFuncAttributeMaxDynamicSharedMemorySize, SMEM_BYTES);
    cudaFuncSetAttribute(attn_fused,        cudaFuncAttributeMaxDynamicSharedMemorySize, SMEM_BYTES);

    // operand splitting (fp16 2-split for all projections)
    conv_a2<<<(S_LEN * DIM / 2 + 255) / 256, 256>>>(x,  x2,  S_LEN * DIM / 2);
    conv_w2<<<(DIM * DIM / 2 + 255) / 256, 256>>>(wq, wq2, DIM * DIM / 2);
    conv_w2<<<(KV_DIM * DIM / 2 + 255) / 256, 256>>>(wk, wk2, KV_DIM * DIM / 2);
    conv_w2<<<(KV_DIM * DIM / 2 + 255) / 256, 256>>>(wv, wv2, KV_DIM * DIM / 2);
    conv_w2<<<(DIM * DIM / 2 + 255) / 256, 256>>>(wo, wo2, DIM * DIM / 2);

    // QKV projections (fp16 2-split)
    gemm_f32_k<true><<<dim3(16, 32), 256, SMEM_BYTES>>>(
        (const __nv_bfloat16*)x2, K2DIM, (const __nv_bfloat16*)wq2, K2DIM, Q, DIM,    K2DIM / BK);
    gemm_f32_k<true><<<dim3(16,  8), 256, SMEM_BYTES>>>(
        (const __nv_bfloat16*)x2, K2DIM, (const __nv_bfloat16*)wk2, K2DIM, K, KV_DIM, K2DIM / BK);
    gemm_f32_k<true><<<dim3(16,  8), 256, SMEM_BYTES>>>(
        (const __nv_bfloat16*)x2, K2DIM, (const __nv_bfloat16*)wv2, K2DIM, V, KV_DIM, K2DIM / BK);

    // RoPE + bf16 3-split for scores; V -> fp16 V^T
    rope_conv_q<<<(S_LEN * NH  * 64) / 256, 256>>>(Q, fc, fs, q3);
    rope_conv_k<<<(S_LEN * NKV * 64) / 256, 256>>>(K, fc, fs, k3);
    conv_vt2<<<dim3(S_LEN / 32, KV_DIM / 32), dim3(32, 8)>>>(V, vt2);

    // fused attention
    attn_fused<<<dim3(16, NH), 256, SMEM_BYTES>>>(q3, k3, vt2, at2);

    // output projection (fp16 2-split)
    gemm_f32_k<true><<<dim3(16, 32), 256, SMEM_BYTES>>>(
        (const __nv_bfloat16*)at2, K2DIM, (const __nv_bfloat16*)wo2, K2DIM, out, DIM, K2DIM / BK);
}